// round 3
// baseline (speedup 1.0000x reference)
#include <cuda_runtime.h>
#include <cuda_bf16.h>
#include <math.h>

#define BN_EPS 1e-5f
#define SLOPE 0.1f

// -------- scratch (device globals; no allocation allowed) --------
__device__ float g_h2[1024 * 128 * 128];   // 64 MB  : conv2 output [n][co][t]
__device__ float g_ms[1024 * 3328];        // 13.6 MB: pooled features
__device__ float g_fc1[1024 * 512];        // 2 MB   : fc1 output

// ============================================================================
// Kernel 1: conv1 (6->64) fully in smem, then conv2 (64->128) as tiled GEMM.
// grid = (2, 1024): blockIdx.x = 64-channel tile of conv2 output, blockIdx.y = n
// 256 threads.  GEMM: M=64 (co tile), N=128 (t), K=192 (ci*3+k).
// Each thread: 8 co x 4 t accumulators; t = tx + 32*j (tx = lane).
// ============================================================================
__global__ __launch_bounds__(256) void conv12_kernel(
    const float* __restrict__ x,
    const float* __restrict__ w1, const float* __restrict__ b1,
    const float* __restrict__ g1, const float* __restrict__ be1,
    const float* __restrict__ m1, const float* __restrict__ v1,
    const float* __restrict__ w2, const float* __restrict__ b2,
    const float* __restrict__ g2, const float* __restrict__ be2,
    const float* __restrict__ m2, const float* __restrict__ v2)
{
    __shared__ float xs[6 * 130];     // input with halo, stride 130, valid t at [1..128]
    __shared__ float h1s[64 * 132];   // h1 with halo, stride 132, valid t at [1..128]
    __shared__ float w1f[64 * 18];    // BN-scale-folded conv1 weights
    __shared__ float sh1[64];
    __shared__ float ws[16 * 64];     // staged conv2 weight chunk [k][co]
    __shared__ float s2[64], sh2[64];

    const int n   = blockIdx.y;
    const int cot = blockIdx.x;          // which 64-co tile of conv2
    const int tid = threadIdx.x;

    if (tid < 64) {
        float a1 = g1[tid] * rsqrtf(v1[tid] + BN_EPS);
        sh1[tid] = a1 * (b1[tid] - m1[tid]) + be1[tid];
        int co = cot * 64 + tid;
        float a2 = g2[co] * rsqrtf(v2[co] + BN_EPS);
        s2[tid]  = a2;
        sh2[tid] = a2 * (b2[co] - m2[co]) + be2[co];
    }
    // fold BN scale into w1
    for (int i = tid; i < 64 * 18; i += 256) {
        int co = i / 18;
        float a = g1[co] * rsqrtf(v1[co] + BN_EPS);
        w1f[i] = a * w1[i];
    }
    // load x: global layout [n][t][c]
    for (int i = tid; i < 768; i += 256) {
        int t = i / 6, c = i - t * 6;
        xs[c * 130 + 1 + t] = x[n * 768 + i];
    }
    if (tid < 6)  { xs[tid * 130] = 0.f; xs[tid * 130 + 129] = 0.f; }
    if (tid < 64) { h1s[tid * 132] = 0.f; h1s[tid * 132 + 129] = 0.f; }
    __syncthreads();

    // ---- conv1 + BN + lrelu -> h1s ----
    #pragma unroll 4
    for (int r = 0; r < 32; ++r) {
        int idx = tid + 256 * r;
        int co = idx >> 7, t = idx & 127;
        float v = sh1[co];
        #pragma unroll
        for (int ci = 0; ci < 6; ++ci)
            #pragma unroll
            for (int k = 0; k < 3; ++k)
                v += w1f[co * 18 + ci * 3 + k] * xs[ci * 130 + t + k];
        h1s[co * 132 + 1 + t] = v > 0.f ? v : SLOPE * v;
    }

    // ---- conv2 GEMM ----
    const int ty = tid >> 5, tx = tid & 31;
    float acc[8][4];
    #pragma unroll
    for (int i = 0; i < 8; ++i)
        #pragma unroll
        for (int j = 0; j < 4; ++j) acc[i][j] = 0.f;

    for (int kc = 0; kc < 12; ++kc) {
        __syncthreads();
        {   // stage 16x64 weight chunk (BN scale folded)
            int kl = tid & 15, cl = tid >> 4;
            #pragma unroll
            for (int rep = 0; rep < 4; ++rep) {
                ws[kl * 64 + cl] = s2[cl] * w2[(cot * 64 + cl) * 192 + kc * 16 + kl];
                cl += 16;
            }
        }
        __syncthreads();
        #pragma unroll
        for (int kk = 0; kk < 16; ++kk) {
            int kabs = kc * 16 + kk;
            int ci = kabs / 3;
            int k  = kabs - ci * 3;
            const float* bp = &h1s[ci * 132 + k + tx];
            float bv[4] = { bp[0], bp[32], bp[64], bp[96] };
            float4 A0 = *(const float4*)&ws[kk * 64 + ty * 8];
            float4 A1 = *(const float4*)&ws[kk * 64 + ty * 8 + 4];
            float a[8] = { A0.x, A0.y, A0.z, A0.w, A1.x, A1.y, A1.z, A1.w };
            #pragma unroll
            for (int i = 0; i < 8; ++i)
                #pragma unroll
                for (int j = 0; j < 4; ++j)
                    acc[i][j] += a[i] * bv[j];
        }
    }

    // epilogue: shift + lrelu -> g_h2
    #pragma unroll
    for (int i = 0; i < 8; ++i) {
        int co_l = ty * 8 + i;
        float sh = sh2[co_l];
        long base = ((long)n * 128 + cot * 64 + co_l) * 128;
        #pragma unroll
        for (int j = 0; j < 4; ++j) {
            float v = acc[i][j] + sh;
            v = v > 0.f ? v : SLOPE * v;
            g_h2[base + tx + 32 * j] = v;
        }
    }
}

// ============================================================================
// Kernel 2: conv3 (128->256) + BN + lrelu + all three adaptive pools, fused.
// grid = (4, 1024): blockIdx.x = 64-co tile, blockIdx.y = n.  256 threads.
// GEMM: M=64, N=128 (t), K=384.  h2 tile lives in dynamic smem.
// Pools done with shfl reductions (t = tx + 32*j => local bin = 2j + tx/16,
// mid bin = j, glob = sum over j).
// ============================================================================
extern __shared__ float h2s[];  // 128 * 132 floats

__global__ __launch_bounds__(256) void conv3_pool_kernel(
    const float* __restrict__ w3, const float* __restrict__ b3,
    const float* __restrict__ g3, const float* __restrict__ be3,
    const float* __restrict__ m3, const float* __restrict__ v3)
{
    __shared__ float ws[16 * 64];
    __shared__ float s3[64], sh3[64];

    const int n   = blockIdx.y;
    const int cot = blockIdx.x;
    const int co0 = cot * 64;
    const int tid = threadIdx.x;

    if (tid < 64) {
        int co = co0 + tid;
        float a = g3[co] * rsqrtf(v3[co] + BN_EPS);
        s3[tid]  = a;
        sh3[tid] = a * (b3[co] - m3[co]) + be3[co];
    }
    // load h2 tile (vectorized) into padded smem
    {
        const float4* src = (const float4*)(g_h2 + (long)n * 16384);
        for (int idx = tid; idx < 4096; idx += 256) {
            int ci = idx >> 5, q = idx & 31;
            float4 v = src[idx];
            float* d = &h2s[ci * 132 + 1 + q * 4];
            d[0] = v.x; d[1] = v.y; d[2] = v.z; d[3] = v.w;
        }
        if (tid < 128) { h2s[tid * 132] = 0.f; h2s[tid * 132 + 129] = 0.f; }
    }

    const int ty = tid >> 5, tx = tid & 31;
    float acc[8][4];
    #pragma unroll
    for (int i = 0; i < 8; ++i)
        #pragma unroll
        for (int j = 0; j < 4; ++j) acc[i][j] = 0.f;

    for (int kc = 0; kc < 24; ++kc) {
        __syncthreads();
        {
            int kl = tid & 15, cl = tid >> 4;
            #pragma unroll
            for (int rep = 0; rep < 4; ++rep) {
                ws[kl * 64 + cl] = s3[cl] * w3[(co0 + cl) * 384 + kc * 16 + kl];
                cl += 16;
            }
        }
        __syncthreads();
        #pragma unroll
        for (int kk = 0; kk < 16; ++kk) {
            int kabs = kc * 16 + kk;
            int ci = kabs / 3;
            int k  = kabs - ci * 3;
            const float* bp = &h2s[ci * 132 + k + tx];
            float bv[4] = { bp[0], bp[32], bp[64], bp[96] };
            float4 A0 = *(const float4*)&ws[kk * 64 + ty * 8];
            float4 A1 = *(const float4*)&ws[kk * 64 + ty * 8 + 4];
            float a[8] = { A0.x, A0.y, A0.z, A0.w, A1.x, A1.y, A1.z, A1.w };
            #pragma unroll
            for (int i = 0; i < 8; ++i)
                #pragma unroll
                for (int j = 0; j < 4; ++j)
                    acc[i][j] += a[i] * bv[j];
        }
    }

    // ---- epilogue: shift + lrelu + pool (warp shfl reductions) ----
    float* msn = g_ms + (long)n * 3328;
    #pragma unroll
    for (int i = 0; i < 8; ++i) {
        int co_l = ty * 8 + i;
        int co_g = co0 + co_l;
        float sh = sh3[co_l];
        float glob = 0.f;
        #pragma unroll
        for (int j = 0; j < 4; ++j) {
            float v = acc[i][j] + sh;
            v = v > 0.f ? v : SLOPE * v;
            float r = v;
            r += __shfl_xor_sync(0xffffffffu, r, 1);
            r += __shfl_xor_sync(0xffffffffu, r, 2);
            r += __shfl_xor_sync(0xffffffffu, r, 4);
            r += __shfl_xor_sync(0xffffffffu, r, 8);
            // r = sum over 16-lane half -> local bin (2j + half)
            float mbin = r + __shfl_xor_sync(0xffffffffu, r, 16); // 32-lane sum -> mid bin j
            if (tx == 0)  msn[co_g * 8 + 2 * j]     = r * (1.f / 16.f);
            if (tx == 16) msn[co_g * 8 + 2 * j + 1] = r * (1.f / 16.f);
            if (tx == 0)  msn[2048 + co_g * 4 + j]  = mbin * (1.f / 32.f);
            glob += mbin;
        }
        if (tx == 0) msn[3072 + co_g] = glob * (1.f / 128.f);
    }
}

// ============================================================================
// Kernel 3: generic GEMM  C[M][N] = act(A[M][K] * B[N][K]^T + bias)
// 64x64 block tile, 256 threads, 4x4 per thread, K chunks of 16.
// ============================================================================
template <bool RELU>
__global__ __launch_bounds__(256) void fc_kernel(
    const float* __restrict__ A, const float* __restrict__ B,
    const float* __restrict__ bias, float* __restrict__ C,
    int M, int N, int K)
{
    __shared__ float As[16 * 64];
    __shared__ float Bs[16 * 64];

    const int tid = threadIdx.x;
    const int m0 = blockIdx.y * 64, n0 = blockIdx.x * 64;
    const int r = tid >> 2, q = tid & 3;       // load map
    const int txm = tid >> 4, txn = tid & 15;  // compute map

    float acc[4][4];
    #pragma unroll
    for (int u = 0; u < 4; ++u)
        #pragma unroll
        for (int v = 0; v < 4; ++v) acc[u][v] = 0.f;

    for (int kb = 0; kb < K; kb += 16) {
        float4 av = *(const float4*)&A[(long)(m0 + r) * K + kb + q * 4];
        float4 bv = *(const float4*)&B[(long)(n0 + r) * K + kb + q * 4];
        __syncthreads();
        As[(q * 4 + 0) * 64 + r] = av.x;
        As[(q * 4 + 1) * 64 + r] = av.y;
        As[(q * 4 + 2) * 64 + r] = av.z;
        As[(q * 4 + 3) * 64 + r] = av.w;
        Bs[(q * 4 + 0) * 64 + r] = bv.x;
        Bs[(q * 4 + 1) * 64 + r] = bv.y;
        Bs[(q * 4 + 2) * 64 + r] = bv.z;
        Bs[(q * 4 + 3) * 64 + r] = bv.w;
        __syncthreads();
        #pragma unroll
        for (int kk = 0; kk < 16; ++kk) {
            float4 a = *(const float4*)&As[kk * 64 + txm * 4];
            float4 b = *(const float4*)&Bs[kk * 64 + txn * 4];
            float aa[4] = { a.x, a.y, a.z, a.w };
            float bb[4] = { b.x, b.y, b.z, b.w };
            #pragma unroll
            for (int u = 0; u < 4; ++u)
                #pragma unroll
                for (int v = 0; v < 4; ++v)
                    acc[u][v] += aa[u] * bb[v];
        }
    }

    float4 bi = *(const float4*)&bias[n0 + txn * 4];
    float bb[4] = { bi.x, bi.y, bi.z, bi.w };
    #pragma unroll
    for (int u = 0; u < 4; ++u) {
        int row = m0 + txm * 4 + u;
        float4 ov;
        float o0 = acc[u][0] + bb[0];
        float o1 = acc[u][1] + bb[1];
        float o2 = acc[u][2] + bb[2];
        float o3 = acc[u][3] + bb[3];
        if (RELU) {
            o0 = fmaxf(o0, 0.f); o1 = fmaxf(o1, 0.f);
            o2 = fmaxf(o2, 0.f); o3 = fmaxf(o3, 0.f);
        }
        ov.x = o0; ov.y = o1; ov.z = o2; ov.w = o3;
        *(float4*)&C[(long)row * N + n0 + txn * 4] = ov;
    }
}

// ============================================================================
// metadata.txt / setup_inputs() dict order:
//   0:x 1:w1 2:b1 3:w2 4:b2 5:w3 6:b3
//   7:g1 8:be1 9:m1 10:v1  11:g2 12:be2 13:m2 14:v2  15:g3 16:be3 17:m3 18:v3
//   19:lw1 20:lb1 21:lw2 22:lb2
// ============================================================================
extern "C" void kernel_launch(void* const* d_in, const int* in_sizes, int n_in,
                              void* d_out, int out_size)
{
    const float* x   = (const float*)d_in[0];
    const float* w1  = (const float*)d_in[1];
    const float* b1  = (const float*)d_in[2];
    const float* w2  = (const float*)d_in[3];
    const float* b2  = (const float*)d_in[4];
    const float* w3  = (const float*)d_in[5];
    const float* b3  = (const float*)d_in[6];
    const float* g1  = (const float*)d_in[7];
    const float* be1 = (const float*)d_in[8];
    const float* m1  = (const float*)d_in[9];
    const float* v1  = (const float*)d_in[10];
    const float* g2  = (const float*)d_in[11];
    const float* be2 = (const float*)d_in[12];
    const float* m2  = (const float*)d_in[13];
    const float* v2  = (const float*)d_in[14];
    const float* g3  = (const float*)d_in[15];
    const float* be3 = (const float*)d_in[16];
    const float* m3  = (const float*)d_in[17];
    const float* v3  = (const float*)d_in[18];
    const float* lw1 = (const float*)d_in[19];
    const float* lb1 = (const float*)d_in[20];
    const float* lw2 = (const float*)d_in[21];
    const float* lb2 = (const float*)d_in[22];
    float* out = (float*)d_out;

    // conv3 kernel needs 128*132*4 = 67584 B of dynamic smem (> 48KB default)
    cudaFuncSetAttribute(conv3_pool_kernel,
                         cudaFuncAttributeMaxDynamicSharedMemorySize, 69632);

    conv12_kernel<<<dim3(2, 1024), 256>>>(x, w1, b1, g1, be1, m1, v1,
                                          w2, b2, g2, be2, m2, v2);
    conv3_pool_kernel<<<dim3(4, 1024), 256, 128 * 132 * sizeof(float)>>>(
        w3, b3, g3, be3, m3, v3);

    float* fc1o;
    float* msp;
    // retrieve device symbol addresses (host-side; capture-safe, no allocation)
    cudaGetSymbolAddress((void**)&msp,  g_ms);
    cudaGetSymbolAddress((void**)&fc1o, g_fc1);

    fc_kernel<true><<<dim3(512 / 64, 1024 / 64), 256>>>(msp, lw1, lb1, fc1o,
                                                        1024, 512, 3328);
    fc_kernel<false><<<dim3(256 / 64, 1024 / 64), 256>>>(fc1o, lw2, lb2, out,
                                                         1024, 256, 512);
}

// round 5
// speedup vs baseline: 1.3523x; 1.3523x over previous
#include <cuda_runtime.h>
#include <cuda_bf16.h>
#include <math.h>
#include <stdint.h>

#define BN_EPS 1e-5f
#define SLOPE 0.1f

// -------- scratch (device globals; no allocation allowed) --------
__device__ float g_h2[1024 * 128 * 128];   // 64 MB  : conv2 output [n][co][t] (tf32-valued)
__device__ float g_ms[1024 * 3328];        // 13.6 MB: pooled features
__device__ float g_fc1[1024 * 512];        // 2 MB   : fc1 output

// ---- helpers ----
__device__ __forceinline__ float tf32r(float x) {
    uint32_t u;
    asm("cvt.rna.tf32.f32 %0, %1;" : "=r"(u) : "f"(x));
    return __uint_as_float(u);
}
__device__ __forceinline__ uint32_t fbits(float x) { return __float_as_uint(x); }

// D += A(16x8,row) * B(8x8,col)   tf32 inputs, f32 accum
__device__ __forceinline__ void mma8(float* d, const uint32_t* a, uint32_t b0, uint32_t b1) {
    asm volatile(
        "mma.sync.aligned.m16n8k8.row.col.f32.tf32.tf32.f32 "
        "{%0,%1,%2,%3}, {%4,%5,%6,%7}, {%8,%9}, {%0,%1,%2,%3};"
        : "+f"(d[0]), "+f"(d[1]), "+f"(d[2]), "+f"(d[3])
        : "r"(a[0]), "r"(a[1]), "r"(a[2]), "r"(a[3]), "r"(b0), "r"(b1));
}
__device__ __forceinline__ float lrelu(float v) { return v > 0.f ? v : SLOPE * v; }

// ============================================================================
// Kernel 1: conv1 (6->64, fp32, in smem) + conv2 (64->128, tf32 mma) per n.
// grid = 1024 (one block per n), 256 threads (8 warps: 4(M) x 2(N)).
// conv2 GEMM: M=128 co, N=128 t, K=192 (tap-major: K = tap*64 + ci).
// Each warp: 32 co x 64 t  (mtiles=2, ntiles=8).
// h1s stride 136 floats (136 mod 32 == 8 -> conflict-free mma fragment loads).
// NOTE: static(17.7KB) + dynamic(34.8KB) > 48KB -> requires opt-in attribute!
// ============================================================================
extern __shared__ float dsm[];

__global__ __launch_bounds__(256) void conv12_kernel(
    const float* __restrict__ x,
    const float* __restrict__ w1, const float* __restrict__ b1,
    const float* __restrict__ g1, const float* __restrict__ be1,
    const float* __restrict__ m1, const float* __restrict__ v1,
    const float* __restrict__ w2, const float* __restrict__ b2,
    const float* __restrict__ g2, const float* __restrict__ be2,
    const float* __restrict__ m2, const float* __restrict__ v2)
{
    float* h1s = dsm;                     // [64][136], valid t at idx 1..128, halo zeros
    __shared__ float xs[6 * 130];         // input halo tile
    __shared__ float w1f[64 * 18];
    __shared__ float sh1[64];
    __shared__ float wsx[16 * 136];       // conv2 weight chunk [kk][co], stride 136
    __shared__ float s2[128], sh2[128];

    const int n   = blockIdx.x;
    const int tid = threadIdx.x;

    if (tid < 64) {
        float a1 = g1[tid] * rsqrtf(v1[tid] + BN_EPS);
        sh1[tid] = a1 * (b1[tid] - m1[tid]) + be1[tid];
    }
    if (tid < 128) {
        float a2 = g2[tid] * rsqrtf(v2[tid] + BN_EPS);
        s2[tid]  = a2;
        sh2[tid] = a2 * (b2[tid] - m2[tid]) + be2[tid];
    }
    for (int i = tid; i < 64 * 18; i += 256) {
        int co = i / 18;
        float a = g1[co] * rsqrtf(v1[co] + BN_EPS);
        w1f[i] = a * w1[i];
    }
    for (int i = tid; i < 768; i += 256) {
        int t = i / 6, c = i - t * 6;
        xs[c * 130 + 1 + t] = x[n * 768 + i];
    }
    if (tid < 6)  { xs[tid * 130] = 0.f; xs[tid * 130 + 129] = 0.f; }
    if (tid < 64) { h1s[tid * 136] = 0.f; h1s[tid * 136 + 129] = 0.f; }
    __syncthreads();

    // ---- conv1 + BN + lrelu -> h1s (tf32-rounded) ----
    #pragma unroll 4
    for (int r = 0; r < 32; ++r) {
        int idx = tid + 256 * r;
        int co = idx >> 7, t = idx & 127;
        float v = sh1[co];
        #pragma unroll
        for (int ci = 0; ci < 6; ++ci)
            #pragma unroll
            for (int k = 0; k < 3; ++k)
                v += w1f[co * 18 + ci * 3 + k] * xs[ci * 130 + t + k];
        h1s[co * 136 + 1 + t] = tf32r(lrelu(v));
    }

    // ---- conv2 via tf32 mma ----
    const int lane = tid & 31, warp = tid >> 5;
    const int wm = warp >> 1;           // 0..3 -> m0 = wm*32
    const int wn = warp & 1;            // 0..1 -> n0 = wn*64
    const int gid = lane >> 2, tig = lane & 3;

    float d[2][8][4];
    #pragma unroll
    for (int mt = 0; mt < 2; ++mt)
        #pragma unroll
        for (int nt = 0; nt < 8; ++nt)
            #pragma unroll
            for (int q = 0; q < 4; ++q) d[mt][nt][q] = 0.f;

    for (int kc = 0; kc < 12; ++kc) {        // 12 chunks of 16 K
        __syncthreads();
        for (int i = tid; i < 16 * 128; i += 256) {
            int kk = i >> 7, co = i & 127;
            int kabs = kc * 16 + kk;
            int tap = kabs >> 6, ci = kabs & 63;
            wsx[kk * 136 + co] = tf32r(s2[co] * w2[co * 192 + ci * 3 + tap]);
        }
        __syncthreads();
        #pragma unroll
        for (int ks = 0; ks < 2; ++ks) {
            int k0  = kc * 16 + ks * 8;
            int tap = k0 >> 6, cib = k0 & 63;
            const float* wr0 = &wsx[(ks * 8 + tig) * 136];
            const float* wr4 = &wsx[(ks * 8 + tig + 4) * 136];
            uint32_t a[2][4];
            #pragma unroll
            for (int mt = 0; mt < 2; ++mt) {
                int m = wm * 32 + mt * 16 + gid;
                a[mt][0] = fbits(wr0[m]);     a[mt][1] = fbits(wr0[m + 8]);
                a[mt][2] = fbits(wr4[m]);     a[mt][3] = fbits(wr4[m + 8]);
            }
            const float* h0 = &h1s[(cib + tig) * 136 + tap];
            const float* h4 = &h1s[(cib + tig + 4) * 136 + tap];
            #pragma unroll
            for (int nt = 0; nt < 8; ++nt) {
                int nn = wn * 64 + nt * 8 + gid;
                uint32_t b0 = fbits(h0[nn]);
                uint32_t b1 = fbits(h4[nn]);
                mma8(d[0][nt], a[0], b0, b1);
                mma8(d[1][nt], a[1], b0, b1);
            }
        }
    }

    // epilogue: shift + lrelu + tf32-round -> g_h2 [n][co][t]
    #pragma unroll
    for (int mt = 0; mt < 2; ++mt) {
        int r0 = wm * 32 + mt * 16 + gid;
        int r1 = r0 + 8;
        float s0 = sh2[r0], s1 = sh2[r1];
        long base0 = ((long)n * 128 + r0) * 128;
        long base1 = ((long)n * 128 + r1) * 128;
        #pragma unroll
        for (int nt = 0; nt < 8; ++nt) {
            int t = wn * 64 + nt * 8 + tig * 2;
            float2 v0 = { tf32r(lrelu(d[mt][nt][0] + s0)), tf32r(lrelu(d[mt][nt][1] + s0)) };
            float2 v1 = { tf32r(lrelu(d[mt][nt][2] + s1)), tf32r(lrelu(d[mt][nt][3] + s1)) };
            *(float2*)&g_h2[base0 + t] = v0;
            *(float2*)&g_h2[base1 + t] = v1;
        }
    }
}

// ============================================================================
// Kernel 2: conv3 (128->256, tf32 mma) + BN + lrelu + fused pools.
// grid = (4, 1024), 256 threads (8 warps: 2(M) x 4(N)), warp = 32 co x 32 t.
// K = 384 tap-major (K = tap*128 + ci).  h2 tile [128][136] in dyn smem.
// ============================================================================
__global__ __launch_bounds__(256) void conv3_pool_kernel(
    const float* __restrict__ w3, const float* __restrict__ b3,
    const float* __restrict__ g3, const float* __restrict__ be3,
    const float* __restrict__ m3, const float* __restrict__ v3)
{
    float* h2s = dsm;                   // [128][136], valid t at 1..128
    __shared__ float ws[16 * 72];       // weight chunk [kk][co], stride 72
    __shared__ float s3[64], sh3[64];
    __shared__ float tot[4 * 64];       // per-n-warp partial sums for global pool

    const int n   = blockIdx.y;
    const int cot = blockIdx.x;
    const int co0 = cot * 64;
    const int tid = threadIdx.x;

    if (tid < 64) {
        int co = co0 + tid;
        float a = g3[co] * rsqrtf(v3[co] + BN_EPS);
        s3[tid]  = a;
        sh3[tid] = a * (b3[co] - m3[co]) + be3[co];
    }
    {   // load h2 tile (already tf32-valued)
        const float4* src = (const float4*)(g_h2 + (long)n * 16384);
        for (int idx = tid; idx < 4096; idx += 256) {
            int ci = idx >> 5, q = idx & 31;
            float4 v = src[idx];
            float* dst = &h2s[ci * 136 + 1 + q * 4];
            dst[0] = v.x; dst[1] = v.y; dst[2] = v.z; dst[3] = v.w;
        }
        if (tid < 128) { h2s[tid * 136] = 0.f; h2s[tid * 136 + 129] = 0.f; }
    }

    const int lane = tid & 31, warp = tid >> 5;
    const int wm = warp >> 2;           // 0..1 -> m0 = wm*32
    const int wn = warp & 3;            // 0..3 -> n0 = wn*32
    const int gid = lane >> 2, tig = lane & 3;

    float d[2][4][4];
    #pragma unroll
    for (int mt = 0; mt < 2; ++mt)
        #pragma unroll
        for (int nt = 0; nt < 4; ++nt)
            #pragma unroll
            for (int q = 0; q < 4; ++q) d[mt][nt][q] = 0.f;

    for (int kc = 0; kc < 24; ++kc) {        // 24 chunks of 16 K
        __syncthreads();
        for (int i = tid; i < 16 * 64; i += 256) {
            int kk = i >> 6, co = i & 63;
            int kabs = kc * 16 + kk;
            int tap = kabs >> 7, ci = kabs & 127;
            ws[kk * 72 + co] = tf32r(s3[co] * w3[(co0 + co) * 384 + ci * 3 + tap]);
        }
        __syncthreads();
        #pragma unroll
        for (int ks = 0; ks < 2; ++ks) {
            int k0  = kc * 16 + ks * 8;
            int tap = k0 >> 7, cib = k0 & 127;
            const float* wr0 = &ws[(ks * 8 + tig) * 72];
            const float* wr4 = &ws[(ks * 8 + tig + 4) * 72];
            uint32_t a[2][4];
            #pragma unroll
            for (int mt = 0; mt < 2; ++mt) {
                int m = wm * 32 + mt * 16 + gid;
                a[mt][0] = fbits(wr0[m]);     a[mt][1] = fbits(wr0[m + 8]);
                a[mt][2] = fbits(wr4[m]);     a[mt][3] = fbits(wr4[m + 8]);
            }
            const float* h0 = &h2s[(cib + tig) * 136 + tap];
            const float* h4 = &h2s[(cib + tig + 4) * 136 + tap];
            #pragma unroll
            for (int nt = 0; nt < 4; ++nt) {
                int nn = wn * 32 + nt * 8 + gid;
                uint32_t b0 = fbits(h0[nn]);
                uint32_t b1 = fbits(h4[nn]);
                mma8(d[0][nt], a[0], b0, b1);
                mma8(d[1][nt], a[1], b0, b1);
            }
        }
    }

    // ---- epilogue: shift + lrelu + pools ----
    // warp covers t in [wn*32, wn*32+32): local bins 2*wn, 2*wn+1; mid bin wn.
    float* msn = g_ms + (long)n * 3328;
    #pragma unroll
    for (int mt = 0; mt < 2; ++mt) {
        int col_l0 = wm * 32 + mt * 16 + gid;    // co within this 64-tile
        int col_l1 = col_l0 + 8;
        float s0 = sh3[col_l0], s1 = sh3[col_l1];
        // per-thread partial bin sums (2 cols per nt)
        float bl0 = 0.f, bh0 = 0.f, bl1 = 0.f, bh1 = 0.f;
        #pragma unroll
        for (int nt = 0; nt < 4; ++nt) {
            float v0 = lrelu(d[mt][nt][0] + s0);
            float v1 = lrelu(d[mt][nt][1] + s0);
            float v2 = lrelu(d[mt][nt][2] + s1);
            float v3_ = lrelu(d[mt][nt][3] + s1);
            if (nt < 2) { bl0 += v0 + v1; bl1 += v2 + v3_; }
            else        { bh0 += v0 + v1; bh1 += v2 + v3_; }
        }
        // reduce over tig (lanes gid*4 .. gid*4+3)
        bl0 += __shfl_xor_sync(0xffffffffu, bl0, 1);
        bl0 += __shfl_xor_sync(0xffffffffu, bl0, 2);
        bh0 += __shfl_xor_sync(0xffffffffu, bh0, 1);
        bh0 += __shfl_xor_sync(0xffffffffu, bh0, 2);
        bl1 += __shfl_xor_sync(0xffffffffu, bl1, 1);
        bl1 += __shfl_xor_sync(0xffffffffu, bl1, 2);
        bh1 += __shfl_xor_sync(0xffffffffu, bh1, 1);
        bh1 += __shfl_xor_sync(0xffffffffu, bh1, 2);
        if (tig == 0) {
            int cg0 = co0 + col_l0, cg1 = co0 + col_l1;
            msn[cg0 * 8 + 2 * wn]     = bl0 * (1.f / 16.f);
            msn[cg0 * 8 + 2 * wn + 1] = bh0 * (1.f / 16.f);
            msn[cg1 * 8 + 2 * wn]     = bl1 * (1.f / 16.f);
            msn[cg1 * 8 + 2 * wn + 1] = bh1 * (1.f / 16.f);
            msn[2048 + cg0 * 4 + wn]  = (bl0 + bh0) * (1.f / 32.f);
            msn[2048 + cg1 * 4 + wn]  = (bl1 + bh1) * (1.f / 32.f);
            tot[wn * 64 + col_l0] = bl0 + bh0;
            tot[wn * 64 + col_l1] = bl1 + bh1;
        }
    }
    __syncthreads();
    if (tid < 64) {
        float g = tot[tid] + tot[64 + tid] + tot[128 + tid] + tot[192 + tid];
        msn[3072 + co0 + tid] = g * (1.f / 128.f);
    }
}

// ============================================================================
// Kernel 3: fc1 via tf32 mma.  C[1024][512] = relu(A[1024][3328] B[512][3328]^T + b)
// 64x64 tiles, 128 threads (4 warps 2x2, warp 32x32).  K chunks of 16.
// ============================================================================
__global__ __launch_bounds__(128) void fc1_mma_kernel(
    const float* __restrict__ A, const float* __restrict__ B,
    const float* __restrict__ bias, float* __restrict__ C)
{
    __shared__ float As[16 * 72];   // [k][m]
    __shared__ float Bs[16 * 72];   // [k][n]

    const int tid = threadIdx.x;
    const int m0 = blockIdx.y * 64, n0 = blockIdx.x * 64;
    const int K = 3328, N = 512;

    const int lane = tid & 31, warp = tid >> 5;
    const int wm = warp >> 1, wn = warp & 1;
    const int gid = lane >> 2, tig = lane & 3;

    const int lr = tid >> 2, lq = tid & 3;   // staging map: 32 rows x 4 k-quads

    float d[2][4][4];
    #pragma unroll
    for (int mt = 0; mt < 2; ++mt)
        #pragma unroll
        for (int nt = 0; nt < 4; ++nt)
            #pragma unroll
            for (int q = 0; q < 4; ++q) d[mt][nt][q] = 0.f;

    for (int kc = 0; kc < 208; ++kc) {
        __syncthreads();
        #pragma unroll
        for (int half = 0; half < 2; ++half) {
            int row = lr + half * 32;
            float4 av = *(const float4*)&A[(long)(m0 + row) * K + kc * 16 + lq * 4];
            float4 bv = *(const float4*)&B[(long)(n0 + row) * K + kc * 16 + lq * 4];
            As[(lq * 4 + 0) * 72 + row] = tf32r(av.x);
            As[(lq * 4 + 1) * 72 + row] = tf32r(av.y);
            As[(lq * 4 + 2) * 72 + row] = tf32r(av.z);
            As[(lq * 4 + 3) * 72 + row] = tf32r(av.w);
            Bs[(lq * 4 + 0) * 72 + row] = tf32r(bv.x);
            Bs[(lq * 4 + 1) * 72 + row] = tf32r(bv.y);
            Bs[(lq * 4 + 2) * 72 + row] = tf32r(bv.z);
            Bs[(lq * 4 + 3) * 72 + row] = tf32r(bv.w);
        }
        __syncthreads();
        #pragma unroll
        for (int ks = 0; ks < 2; ++ks) {
            const float* ar0 = &As[(ks * 8 + tig) * 72];
            const float* ar4 = &As[(ks * 8 + tig + 4) * 72];
            const float* br0 = &Bs[(ks * 8 + tig) * 72];
            const float* br4 = &Bs[(ks * 8 + tig + 4) * 72];
            uint32_t a[2][4];
            #pragma unroll
            for (int mt = 0; mt < 2; ++mt) {
                int m = wm * 32 + mt * 16 + gid;
                a[mt][0] = fbits(ar0[m]);  a[mt][1] = fbits(ar0[m + 8]);
                a[mt][2] = fbits(ar4[m]);  a[mt][3] = fbits(ar4[m + 8]);
            }
            #pragma unroll
            for (int nt = 0; nt < 4; ++nt) {
                int nn = wn * 32 + nt * 8 + gid;
                uint32_t b0 = fbits(br0[nn]);
                uint32_t b1 = fbits(br4[nn]);
                mma8(d[0][nt], a[0], b0, b1);
                mma8(d[1][nt], a[1], b0, b1);
            }
        }
    }

    // epilogue: bias + relu
    #pragma unroll
    for (int mt = 0; mt < 2; ++mt) {
        int r0 = m0 + wm * 32 + mt * 16 + gid;
        int r1 = r0 + 8;
        #pragma unroll
        for (int nt = 0; nt < 4; ++nt) {
            int nn = n0 + wn * 32 + nt * 8 + tig * 2;
            float bb0 = bias[nn], bb1 = bias[nn + 1];
            float2 v0 = { fmaxf(d[mt][nt][0] + bb0, 0.f), fmaxf(d[mt][nt][1] + bb1, 0.f) };
            float2 v1 = { fmaxf(d[mt][nt][2] + bb0, 0.f), fmaxf(d[mt][nt][3] + bb1, 0.f) };
            *(float2*)&C[(long)r0 * N + nn] = v0;
            *(float2*)&C[(long)r1 * N + nn] = v1;
        }
    }
}

// ============================================================================
// Kernel 4: fp32 GEMM for fc2.  C = A[M][K] * B[N][K]^T + bias.
// ============================================================================
__global__ __launch_bounds__(256) void fc2_kernel(
    const float* __restrict__ A, const float* __restrict__ B,
    const float* __restrict__ bias, float* __restrict__ C,
    int M, int N, int K)
{
    __shared__ float As[16 * 64];
    __shared__ float Bs[16 * 64];

    const int tid = threadIdx.x;
    const int m0 = blockIdx.y * 64, n0 = blockIdx.x * 64;
    const int r = tid >> 2, q = tid & 3;
    const int txm = tid >> 4, txn = tid & 15;

    float acc[4][4];
    #pragma unroll
    for (int u = 0; u < 4; ++u)
        #pragma unroll
        for (int v = 0; v < 4; ++v) acc[u][v] = 0.f;

    for (int kb = 0; kb < K; kb += 16) {
        float4 av = *(const float4*)&A[(long)(m0 + r) * K + kb + q * 4];
        float4 bv = *(const float4*)&B[(long)(n0 + r) * K + kb + q * 4];
        __syncthreads();
        As[(q * 4 + 0) * 64 + r] = av.x;
        As[(q * 4 + 1) * 64 + r] = av.y;
        As[(q * 4 + 2) * 64 + r] = av.z;
        As[(q * 4 + 3) * 64 + r] = av.w;
        Bs[(q * 4 + 0) * 64 + r] = bv.x;
        Bs[(q * 4 + 1) * 64 + r] = bv.y;
        Bs[(q * 4 + 2) * 64 + r] = bv.z;
        Bs[(q * 4 + 3) * 64 + r] = bv.w;
        __syncthreads();
        #pragma unroll
        for (int kk = 0; kk < 16; ++kk) {
            float4 a = *(const float4*)&As[kk * 64 + txm * 4];
            float4 b = *(const float4*)&Bs[kk * 64 + txn * 4];
            float aa[4] = { a.x, a.y, a.z, a.w };
            float bb[4] = { b.x, b.y, b.z, b.w };
            #pragma unroll
            for (int u = 0; u < 4; ++u)
                #pragma unroll
                for (int v = 0; v < 4; ++v)
                    acc[u][v] += aa[u] * bb[v];
        }
    }

    float4 bi = *(const float4*)&bias[n0 + txn * 4];
    float bb[4] = { bi.x, bi.y, bi.z, bi.w };
    #pragma unroll
    for (int u = 0; u < 4; ++u) {
        int row = m0 + txm * 4 + u;
        float4 ov;
        ov.x = acc[u][0] + bb[0];
        ov.y = acc[u][1] + bb[1];
        ov.z = acc[u][2] + bb[2];
        ov.w = acc[u][3] + bb[3];
        *(float4*)&C[(long)row * N + n0 + txn * 4] = ov;
    }
}

// ============================================================================
// metadata.txt / setup_inputs() dict order:
//   0:x 1:w1 2:b1 3:w2 4:b2 5:w3 6:b3
//   7:g1 8:be1 9:m1 10:v1  11:g2 12:be2 13:m2 14:v2  15:g3 16:be3 17:m3 18:v3
//   19:lw1 20:lb1 21:lw2 22:lb2
// ============================================================================
extern "C" void kernel_launch(void* const* d_in, const int* in_sizes, int n_in,
                              void* d_out, int out_size)
{
    const float* x   = (const float*)d_in[0];
    const float* w1  = (const float*)d_in[1];
    const float* b1  = (const float*)d_in[2];
    const float* w2  = (const float*)d_in[3];
    const float* b2  = (const float*)d_in[4];
    const float* w3  = (const float*)d_in[5];
    const float* b3  = (const float*)d_in[6];
    const float* g1  = (const float*)d_in[7];
    const float* be1 = (const float*)d_in[8];
    const float* m1  = (const float*)d_in[9];
    const float* v1  = (const float*)d_in[10];
    const float* g2  = (const float*)d_in[11];
    const float* be2 = (const float*)d_in[12];
    const float* m2  = (const float*)d_in[13];
    const float* v2  = (const float*)d_in[14];
    const float* g3  = (const float*)d_in[15];
    const float* be3 = (const float*)d_in[16];
    const float* m3  = (const float*)d_in[17];
    const float* v3  = (const float*)d_in[18];
    const float* lw1 = (const float*)d_in[19];
    const float* lb1 = (const float*)d_in[20];
    const float* lw2 = (const float*)d_in[21];
    const float* lb2 = (const float*)d_in[22];
    float* out = (float*)d_out;

    // BOTH dynamic-smem kernels need the opt-in: static + dynamic > 48KB.
    cudaFuncSetAttribute(conv12_kernel,
                         cudaFuncAttributeMaxDynamicSharedMemorySize, 64 * 136 * 4);
    cudaFuncSetAttribute(conv3_pool_kernel,
                         cudaFuncAttributeMaxDynamicSharedMemorySize, 128 * 136 * 4);

    conv12_kernel<<<1024, 256, 64 * 136 * sizeof(float)>>>(
        x, w1, b1, g1, be1, m1, v1, w2, b2, g2, be2, m2, v2);
    conv3_pool_kernel<<<dim3(4, 1024), 256, 128 * 136 * sizeof(float)>>>(
        w3, b3, g3, be3, m3, v3);

    float* fc1o;
    float* msp;
    cudaGetSymbolAddress((void**)&msp,  g_ms);
    cudaGetSymbolAddress((void**)&fc1o, g_fc1);

    fc1_mma_kernel<<<dim3(512 / 64, 1024 / 64), 128>>>(msp, lw1, lb1, fc1o);
    fc2_kernel<<<dim3(256 / 64, 1024 / 64), 256>>>(fc1o, lw2, lb2, out,
                                                   1024, 256, 512);
}

// round 6
// speedup vs baseline: 1.4831x; 1.0967x over previous
#include <cuda_runtime.h>
#include <cuda_bf16.h>
#include <math.h>
#include <stdint.h>

#define BN_EPS 1e-5f
#define SLOPE 0.1f

// -------- scratch (device globals; no allocation allowed) --------
__device__ float g_ms[1024 * 3328];        // pooled features
__device__ float g_fc1[1024 * 512];        // fc1 output

// ---- helpers ----
__device__ __forceinline__ float tf32r(float x) {
    uint32_t u;
    asm("cvt.rna.tf32.f32 %0, %1;" : "=r"(u) : "f"(x));
    return __uint_as_float(u);
}
__device__ __forceinline__ uint32_t fbits(float x) { return __float_as_uint(x); }

// D += A(16x8,row) * B(8x8,col)   tf32 inputs, f32 accum
__device__ __forceinline__ void mma8(float* d, const uint32_t* a, uint32_t b0, uint32_t b1) {
    asm volatile(
        "mma.sync.aligned.m16n8k8.row.col.f32.tf32.tf32.f32 "
        "{%0,%1,%2,%3}, {%4,%5,%6,%7}, {%8,%9}, {%0,%1,%2,%3};"
        : "+f"(d[0]), "+f"(d[1]), "+f"(d[2]), "+f"(d[3])
        : "r"(a[0]), "r"(a[1]), "r"(a[2]), "r"(a[3]), "r"(b0), "r"(b1));
}
__device__ __forceinline__ float lrelu(float v) { return v > 0.f ? v : SLOPE * v; }

// ============================================================================
// FUSED kernel: conv1 (fp32) -> conv2 (tf32 mma) -> conv3 (tf32 mma) -> pools.
// grid = 1024 (one block per sequence n), 256 threads (8 warps: 4(M) x 2(N)).
// h1 [64][136] and h2 [128][136] both live in dynamic smem; no global
// intermediate at all.  K is tap-major: conv2 K = tap*64+ci, conv3 K = tap*128+ci
// (groups of 8 never cross a tap boundary).
// Strides 136 / 264 are ==8 (mod 32) -> conflict-free mma fragment loads.
// ============================================================================
extern __shared__ float dsm[];

__global__ __launch_bounds__(256) void fused_conv_kernel(
    const float* __restrict__ x,
    const float* __restrict__ w1, const float* __restrict__ b1,
    const float* __restrict__ g1, const float* __restrict__ be1,
    const float* __restrict__ m1, const float* __restrict__ v1,
    const float* __restrict__ w2, const float* __restrict__ b2,
    const float* __restrict__ g2, const float* __restrict__ be2,
    const float* __restrict__ m2, const float* __restrict__ v2,
    const float* __restrict__ w3, const float* __restrict__ b3,
    const float* __restrict__ g3, const float* __restrict__ be3,
    const float* __restrict__ m3, const float* __restrict__ v3)
{
    float* h1s = dsm;                 // [64][136], valid t at 1..128, halo zeros
    float* h2s = dsm + 64 * 136;      // [128][136], same layout
    __shared__ float xs[6 * 130];
    __shared__ float w1f[64 * 18];
    __shared__ float sh1[64];
    __shared__ float ws[16 * 264];    // weight chunk buffer (conv2 uses stride 136)
    __shared__ float s2[128], sh2[128];
    __shared__ float s3[256], sh3[256];
    __shared__ float tot[2 * 256];

    const int n   = blockIdx.x;
    const int tid = threadIdx.x;

    // ---- scales / weight folds / input tile ----
    if (tid < 64) {
        float a1 = g1[tid] * rsqrtf(v1[tid] + BN_EPS);
        sh1[tid] = a1 * (b1[tid] - m1[tid]) + be1[tid];
    }
    if (tid < 128) {
        float a2 = g2[tid] * rsqrtf(v2[tid] + BN_EPS);
        s2[tid]  = a2;
        sh2[tid] = a2 * (b2[tid] - m2[tid]) + be2[tid];
    }
    {
        float a3 = g3[tid] * rsqrtf(v3[tid] + BN_EPS);
        s3[tid]  = a3;
        sh3[tid] = a3 * (b3[tid] - m3[tid]) + be3[tid];
    }
    for (int i = tid; i < 64 * 18; i += 256) {
        int co = i / 18;
        float a = g1[co] * rsqrtf(v1[co] + BN_EPS);
        w1f[i] = a * w1[i];
    }
    for (int i = tid; i < 768; i += 256) {
        int t = i / 6, c = i - t * 6;
        xs[c * 130 + 1 + t] = x[n * 768 + i];
    }
    if (tid < 6)   { xs[tid * 130] = 0.f; xs[tid * 130 + 129] = 0.f; }
    if (tid < 64)  { h1s[tid * 136] = 0.f; h1s[tid * 136 + 129] = 0.f; }
    if (tid < 128) { h2s[tid * 136] = 0.f; h2s[tid * 136 + 129] = 0.f; }
    __syncthreads();

    // ---- conv1 + BN + lrelu -> h1s (tf32-rounded) ----
    #pragma unroll 4
    for (int r = 0; r < 32; ++r) {
        int idx = tid + 256 * r;
        int co = idx >> 7, t = idx & 127;
        float v = sh1[co];
        #pragma unroll
        for (int ci = 0; ci < 6; ++ci)
            #pragma unroll
            for (int k = 0; k < 3; ++k)
                v += w1f[co * 18 + ci * 3 + k] * xs[ci * 130 + t + k];
        h1s[co * 136 + 1 + t] = tf32r(lrelu(v));
    }

    const int lane = tid & 31, warp = tid >> 5;
    const int wm = warp >> 1;            // 0..3
    const int wn = warp & 1;             // 0..1
    const int gid = lane >> 2, tig = lane & 3;

    // ================== conv2: M=128 co, N=128 t, K=192 ==================
    // warp tile = 32 co (wm*32) x 64 t (wn*64)
    {
        float d2[2][8][4];
        #pragma unroll
        for (int mt = 0; mt < 2; ++mt)
            #pragma unroll
            for (int nt = 0; nt < 8; ++nt)
                #pragma unroll
                for (int q = 0; q < 4; ++q) d2[mt][nt][q] = 0.f;

        for (int kc = 0; kc < 12; ++kc) {
            __syncthreads();
            for (int i = tid; i < 16 * 128; i += 256) {
                int kk = i >> 7, co = i & 127;
                int kabs = kc * 16 + kk;
                int tap = kabs >> 6, ci = kabs & 63;
                ws[kk * 136 + co] = tf32r(s2[co] * w2[co * 192 + ci * 3 + tap]);
            }
            __syncthreads();
            #pragma unroll
            for (int ks = 0; ks < 2; ++ks) {
                int k0  = kc * 16 + ks * 8;
                int tap = k0 >> 6, cib = k0 & 63;
                const float* wr0 = &ws[(ks * 8 + tig) * 136];
                const float* wr4 = &ws[(ks * 8 + tig + 4) * 136];
                uint32_t a[2][4];
                #pragma unroll
                for (int mt = 0; mt < 2; ++mt) {
                    int m = wm * 32 + mt * 16 + gid;
                    a[mt][0] = fbits(wr0[m]);     a[mt][1] = fbits(wr0[m + 8]);
                    a[mt][2] = fbits(wr4[m]);     a[mt][3] = fbits(wr4[m + 8]);
                }
                const float* h0 = &h1s[(cib + tig) * 136 + tap];
                const float* h4 = &h1s[(cib + tig + 4) * 136 + tap];
                #pragma unroll
                for (int nt = 0; nt < 8; ++nt) {
                    int nn = wn * 64 + nt * 8 + gid;
                    uint32_t b0 = fbits(h0[nn]);
                    uint32_t b1 = fbits(h4[nn]);
                    mma8(d2[0][nt], a[0], b0, b1);
                    mma8(d2[1][nt], a[1], b0, b1);
                }
            }
        }

        // epilogue: shift + lrelu + tf32-round -> h2s (smem, +1 halo offset)
        __syncthreads();   // all warps done reading ws before we proceed
        #pragma unroll
        for (int mt = 0; mt < 2; ++mt) {
            int r0 = wm * 32 + mt * 16 + gid;
            int r1 = r0 + 8;
            float s0 = sh2[r0], s1 = sh2[r1];
            #pragma unroll
            for (int nt = 0; nt < 8; ++nt) {
                int t = wn * 64 + nt * 8 + tig * 2;
                h2s[r0 * 136 + 1 + t]     = tf32r(lrelu(d2[mt][nt][0] + s0));
                h2s[r0 * 136 + 2 + t]     = tf32r(lrelu(d2[mt][nt][1] + s0));
                h2s[r1 * 136 + 1 + t]     = tf32r(lrelu(d2[mt][nt][2] + s1));
                h2s[r1 * 136 + 2 + t]     = tf32r(lrelu(d2[mt][nt][3] + s1));
            }
        }
    }

    // ================== conv3: M=256 co, N=128 t, K=384 ==================
    // warp tile = 64 co (wm*64) x 64 t (wn*64)
    float d3[4][8][4];
    #pragma unroll
    for (int mt = 0; mt < 4; ++mt)
        #pragma unroll
        for (int nt = 0; nt < 8; ++nt)
            #pragma unroll
            for (int q = 0; q < 4; ++q) d3[mt][nt][q] = 0.f;

    for (int kc = 0; kc < 24; ++kc) {
        __syncthreads();   // h2s writes visible (first iter) / ws reads done
        for (int i = tid; i < 16 * 256; i += 256) {
            int kk = i >> 8, co = i & 255;
            int kabs = kc * 16 + kk;
            int tap = kabs >> 7, ci = kabs & 127;
            ws[kk * 264 + co] = tf32r(s3[co] * w3[co * 384 + ci * 3 + tap]);
        }
        __syncthreads();
        #pragma unroll
        for (int ks = 0; ks < 2; ++ks) {
            int k0  = kc * 16 + ks * 8;
            int tap = k0 >> 7, cib = k0 & 127;
            const float* wr0 = &ws[(ks * 8 + tig) * 264];
            const float* wr4 = &ws[(ks * 8 + tig + 4) * 264];
            uint32_t a[4][4];
            #pragma unroll
            for (int mt = 0; mt < 4; ++mt) {
                int m = wm * 64 + mt * 16 + gid;
                a[mt][0] = fbits(wr0[m]);     a[mt][1] = fbits(wr0[m + 8]);
                a[mt][2] = fbits(wr4[m]);     a[mt][3] = fbits(wr4[m + 8]);
            }
            const float* h0 = &h2s[(cib + tig) * 136 + tap];
            const float* h4 = &h2s[(cib + tig + 4) * 136 + tap];
            #pragma unroll
            for (int nt = 0; nt < 8; ++nt) {
                int nn = wn * 64 + nt * 8 + gid;
                uint32_t b0 = fbits(h0[nn]);
                uint32_t b1 = fbits(h4[nn]);
                #pragma unroll
                for (int mt = 0; mt < 4; ++mt)
                    mma8(d3[mt][nt], a[mt], b0, b1);
            }
        }
    }

    // ---- epilogue: shift + lrelu + pools ----
    // t = wn*64 + nt*8 + tig*2 + {0,1}.  local bin = wn*4 + nt/2; mid = wn*2 + nt/4.
    float* msn = g_ms + (long)n * 3328;
    #pragma unroll
    for (int mt = 0; mt < 4; ++mt) {
        int cl0 = wm * 64 + mt * 16 + gid;   // co 0..255
        int cl1 = cl0 + 8;
        float s0 = sh3[cl0], s1 = sh3[cl1];
        float p0[4] = {0.f, 0.f, 0.f, 0.f};
        float p1[4] = {0.f, 0.f, 0.f, 0.f};
        #pragma unroll
        for (int nt = 0; nt < 8; ++nt) {
            int u = nt >> 1;
            p0[u] += lrelu(d3[mt][nt][0] + s0) + lrelu(d3[mt][nt][1] + s0);
            p1[u] += lrelu(d3[mt][nt][2] + s1) + lrelu(d3[mt][nt][3] + s1);
        }
        #pragma unroll
        for (int u = 0; u < 4; ++u) {
            p0[u] += __shfl_xor_sync(0xffffffffu, p0[u], 1);
            p0[u] += __shfl_xor_sync(0xffffffffu, p0[u], 2);
            p1[u] += __shfl_xor_sync(0xffffffffu, p1[u], 1);
            p1[u] += __shfl_xor_sync(0xffffffffu, p1[u], 2);
        }
        if (tig == 0) {
            #pragma unroll
            for (int u = 0; u < 4; ++u) {
                msn[cl0 * 8 + wn * 4 + u] = p0[u] * (1.f / 16.f);
                msn[cl1 * 8 + wn * 4 + u] = p1[u] * (1.f / 16.f);
            }
            msn[2048 + cl0 * 4 + wn * 2 + 0] = (p0[0] + p0[1]) * (1.f / 32.f);
            msn[2048 + cl0 * 4 + wn * 2 + 1] = (p0[2] + p0[3]) * (1.f / 32.f);
            msn[2048 + cl1 * 4 + wn * 2 + 0] = (p1[0] + p1[1]) * (1.f / 32.f);
            msn[2048 + cl1 * 4 + wn * 2 + 1] = (p1[2] + p1[3]) * (1.f / 32.f);
            tot[wn * 256 + cl0] = p0[0] + p0[1] + p0[2] + p0[3];
            tot[wn * 256 + cl1] = p1[0] + p1[1] + p1[2] + p1[3];
        }
    }
    __syncthreads();
    msn[3072 + tid] = (tot[tid] + tot[256 + tid]) * (1.f / 128.f);
}

// ============================================================================
// FC kernel (tf32 mma, double-buffered smem, register prefetch).
// C[M][Nc] = act(A[M][K] * B[Nc][K]^T + bias), 64x64 tile, 256 threads.
// 8 warps as 2(M)x4(N): warp tile 32m x 16n.  One __syncthreads per K-chunk.
// ============================================================================
template <int K, int Nc, bool RELU>
__global__ __launch_bounds__(256) void fc_mma_kernel(
    const float* __restrict__ A, const float* __restrict__ B,
    const float* __restrict__ bias, float* __restrict__ C)
{
    __shared__ float As[2][16 * 72];   // [k][m], stride 72
    __shared__ float Bs[2][16 * 72];

    const int tid = threadIdx.x;
    const int m0 = blockIdx.y * 64, n0 = blockIdx.x * 64;
    const int lane = tid & 31, warp = tid >> 5;
    const int wm = warp >> 2, wn = warp & 3;
    const int gid = lane >> 2, tig = lane & 3;
    const int row = tid >> 2, q = tid & 3;   // staging: 64 rows x 4 k-quads

    const float* Ap = &A[(long)(m0 + row) * K + q * 4];
    const float* Bp = &B[(long)(n0 + row) * K + q * 4];

    float d[2][2][4];
    #pragma unroll
    for (int mt = 0; mt < 2; ++mt)
        #pragma unroll
        for (int nt = 0; nt < 2; ++nt)
            #pragma unroll
            for (int qq = 0; qq < 4; ++qq) d[mt][nt][qq] = 0.f;

    float4 av = *(const float4*)Ap;
    float4 bv = *(const float4*)Bp;
    {
        As[0][(q * 4 + 0) * 72 + row] = tf32r(av.x);
        As[0][(q * 4 + 1) * 72 + row] = tf32r(av.y);
        As[0][(q * 4 + 2) * 72 + row] = tf32r(av.z);
        As[0][(q * 4 + 3) * 72 + row] = tf32r(av.w);
        Bs[0][(q * 4 + 0) * 72 + row] = tf32r(bv.x);
        Bs[0][(q * 4 + 1) * 72 + row] = tf32r(bv.y);
        Bs[0][(q * 4 + 2) * 72 + row] = tf32r(bv.z);
        Bs[0][(q * 4 + 3) * 72 + row] = tf32r(bv.w);
    }
    __syncthreads();

    const int NC = K / 16;
    for (int kc = 0; kc < NC; ++kc) {
        int p = kc & 1;
        if (kc + 1 < NC) {
            av = *(const float4*)(Ap + (kc + 1) * 16);
            bv = *(const float4*)(Bp + (kc + 1) * 16);
        }
        #pragma unroll
        for (int ks = 0; ks < 2; ++ks) {
            const float* ar0 = &As[p][(ks * 8 + tig) * 72];
            const float* ar4 = &As[p][(ks * 8 + tig + 4) * 72];
            const float* br0 = &Bs[p][(ks * 8 + tig) * 72];
            const float* br4 = &Bs[p][(ks * 8 + tig + 4) * 72];
            uint32_t a[2][4];
            #pragma unroll
            for (int mt = 0; mt < 2; ++mt) {
                int m = wm * 32 + mt * 16 + gid;
                a[mt][0] = fbits(ar0[m]);  a[mt][1] = fbits(ar0[m + 8]);
                a[mt][2] = fbits(ar4[m]);  a[mt][3] = fbits(ar4[m + 8]);
            }
            #pragma unroll
            for (int nt = 0; nt < 2; ++nt) {
                int nn = wn * 16 + nt * 8 + gid;
                uint32_t b0 = fbits(br0[nn]);
                uint32_t b1 = fbits(br4[nn]);
                mma8(d[0][nt], a[0], b0, b1);
                mma8(d[1][nt], a[1], b0, b1);
            }
        }
        if (kc + 1 < NC) {
            int pn = p ^ 1;
            As[pn][(q * 4 + 0) * 72 + row] = tf32r(av.x);
            As[pn][(q * 4 + 1) * 72 + row] = tf32r(av.y);
            As[pn][(q * 4 + 2) * 72 + row] = tf32r(av.z);
            As[pn][(q * 4 + 3) * 72 + row] = tf32r(av.w);
            Bs[pn][(q * 4 + 0) * 72 + row] = tf32r(bv.x);
            Bs[pn][(q * 4 + 1) * 72 + row] = tf32r(bv.y);
            Bs[pn][(q * 4 + 2) * 72 + row] = tf32r(bv.z);
            Bs[pn][(q * 4 + 3) * 72 + row] = tf32r(bv.w);
        }
        __syncthreads();
    }

    // epilogue
    #pragma unroll
    for (int mt = 0; mt < 2; ++mt) {
        int r0 = m0 + wm * 32 + mt * 16 + gid;
        int r1 = r0 + 8;
        #pragma unroll
        for (int nt = 0; nt < 2; ++nt) {
            int nn = n0 + wn * 16 + nt * 8 + tig * 2;
            float bb0 = bias[nn], bb1 = bias[nn + 1];
            float o0 = d[mt][nt][0] + bb0, o1 = d[mt][nt][1] + bb1;
            float o2 = d[mt][nt][2] + bb0, o3 = d[mt][nt][3] + bb1;
            if (RELU) {
                o0 = fmaxf(o0, 0.f); o1 = fmaxf(o1, 0.f);
                o2 = fmaxf(o2, 0.f); o3 = fmaxf(o3, 0.f);
            }
            float2 v0 = { o0, o1 }, v1 = { o2, o3 };
            *(float2*)&C[(long)r0 * Nc + nn] = v0;
            *(float2*)&C[(long)r1 * Nc + nn] = v1;
        }
    }
}

// ============================================================================
// metadata.txt / setup_inputs() dict order:
//   0:x 1:w1 2:b1 3:w2 4:b2 5:w3 6:b3
//   7:g1 8:be1 9:m1 10:v1  11:g2 12:be2 13:m2 14:v2  15:g3 16:be3 17:m3 18:v3
//   19:lw1 20:lb1 21:lw2 22:lb2
// ============================================================================
extern "C" void kernel_launch(void* const* d_in, const int* in_sizes, int n_in,
                              void* d_out, int out_size)
{
    const float* x   = (const float*)d_in[0];
    const float* w1  = (const float*)d_in[1];
    const float* b1  = (const float*)d_in[2];
    const float* w2  = (const float*)d_in[3];
    const float* b2  = (const float*)d_in[4];
    const float* w3  = (const float*)d_in[5];
    const float* b3  = (const float*)d_in[6];
    const float* g1  = (const float*)d_in[7];
    const float* be1 = (const float*)d_in[8];
    const float* m1  = (const float*)d_in[9];
    const float* v1  = (const float*)d_in[10];
    const float* g2  = (const float*)d_in[11];
    const float* be2 = (const float*)d_in[12];
    const float* m2  = (const float*)d_in[13];
    const float* v2  = (const float*)d_in[14];
    const float* g3  = (const float*)d_in[15];
    const float* be3 = (const float*)d_in[16];
    const float* m3  = (const float*)d_in[17];
    const float* v3  = (const float*)d_in[18];
    const float* lw1 = (const float*)d_in[19];
    const float* lb1 = (const float*)d_in[20];
    const float* lw2 = (const float*)d_in[21];
    const float* lb2 = (const float*)d_in[22];
    float* out = (float*)d_out;

    const int fused_dyn = (64 * 136 + 128 * 136) * sizeof(float);  // 104448
    cudaFuncSetAttribute(fused_conv_kernel,
                         cudaFuncAttributeMaxDynamicSharedMemorySize, fused_dyn);

    fused_conv_kernel<<<1024, 256, fused_dyn>>>(
        x, w1, b1, g1, be1, m1, v1,
        w2, b2, g2, be2, m2, v2,
        w3, b3, g3, be3, m3, v3);

    float* fc1o;
    float* msp;
    cudaGetSymbolAddress((void**)&msp,  g_ms);
    cudaGetSymbolAddress((void**)&fc1o, g_fc1);

    fc_mma_kernel<3328, 512, true><<<dim3(8, 16), 256>>>(msp, lw1, lb1, fc1o);
    fc_mma_kernel<512, 256, false><<<dim3(4, 16), 256>>>(fc1o, lw2, lb2, out);
}

// round 7
// speedup vs baseline: 3.1759x; 2.1413x over previous
#include <cuda_runtime.h>
#include <cuda_bf16.h>
#include <math.h>
#include <stdint.h>

#define BN_EPS 1e-5f
#define SLOPE 0.1f

// -------- scratch (device globals; no allocation allowed) --------
__device__ float g_ms[1024 * 3328];        // pooled features
__device__ float g_fc1[1024 * 512];        // fc1 output
__device__ float g_w2t[192 * 128];         // conv2 weights: BN-folded, tf32, [kabs][co]
__device__ float g_w3t[384 * 256];         // conv3 weights: BN-folded, tf32, [kabs][co]

// ---- helpers ----
__device__ __forceinline__ float tf32r(float x) {
    uint32_t u;
    asm("cvt.rna.tf32.f32 %0, %1;" : "=r"(u) : "f"(x));
    return __uint_as_float(u);
}
__device__ __forceinline__ uint32_t fbits(float x) { return __float_as_uint(x); }

// D += A(16x8,row) * B(8x8,col)   tf32 inputs, f32 accum
__device__ __forceinline__ void mma8(float* d, const uint32_t* a, uint32_t b0, uint32_t b1) {
    asm volatile(
        "mma.sync.aligned.m16n8k8.row.col.f32.tf32.tf32.f32 "
        "{%0,%1,%2,%3}, {%4,%5,%6,%7}, {%8,%9}, {%0,%1,%2,%3};"
        : "+f"(d[0]), "+f"(d[1]), "+f"(d[2]), "+f"(d[3])
        : "r"(a[0]), "r"(a[1]), "r"(a[2]), "r"(a[3]), "r"(b0), "r"(b1));
}
__device__ __forceinline__ float lrelu(float v) { return v > 0.f ? v : SLOPE * v; }

// ============================================================================
// Prep kernel: fold BN scale into w2/w3, tf32-round, transpose to tap-major
// [kabs][co] layout (co contiguous -> coalesced staging in the fused kernel).
// Runs once per launch; ~123K elements total, trivial cost.
// ============================================================================
__global__ __launch_bounds__(256) void prep_weights_kernel(
    const float* __restrict__ w2, const float* __restrict__ g2, const float* __restrict__ v2,
    const float* __restrict__ w3, const float* __restrict__ g3, const float* __restrict__ v3)
{
    int i = blockIdx.x * 256 + threadIdx.x;
    if (i < 192 * 128) {
        int kabs = i >> 7, co = i & 127;
        int tap = kabs >> 6, ci = kabs & 63;
        float a = g2[co] * rsqrtf(v2[co] + BN_EPS);
        g_w2t[i] = tf32r(a * w2[co * 192 + ci * 3 + tap]);
    }
    if (i < 384 * 256) {
        int kabs = i >> 8, co = i & 255;
        int tap = kabs >> 7, ci = kabs & 127;
        float a = g3[co] * rsqrtf(v3[co] + BN_EPS);
        g_w3t[i] = tf32r(a * w3[co * 384 + ci * 3 + tap]);
    }
}

// ============================================================================
// FUSED kernel: conv1 (fp32) -> conv2 (tf32 mma) -> conv3 (tf32 mma) -> pools.
// grid = 1024 (one block per sequence n), 256 threads (8 warps: 4(M) x 2(N)).
// Weight staging is now a coalesced float4 copy from pre-folded g_w2t/g_w3t.
// ============================================================================
extern __shared__ float dsm[];

__global__ __launch_bounds__(256) void fused_conv_kernel(
    const float* __restrict__ x,
    const float* __restrict__ w1, const float* __restrict__ b1,
    const float* __restrict__ g1, const float* __restrict__ be1,
    const float* __restrict__ m1, const float* __restrict__ v1,
    const float* __restrict__ b2,
    const float* __restrict__ g2, const float* __restrict__ be2,
    const float* __restrict__ m2, const float* __restrict__ v2,
    const float* __restrict__ b3,
    const float* __restrict__ g3, const float* __restrict__ be3,
    const float* __restrict__ m3, const float* __restrict__ v3)
{
    float* h1s = dsm;                 // [64][136], valid t at 1..128, halo zeros
    float* h2s = dsm + 64 * 136;      // [128][136], same layout
    __shared__ float xs[6 * 130];
    __shared__ float w1f[64 * 18];
    __shared__ float sh1[64];
    __shared__ float ws[16 * 264];    // weight chunk buffer (conv2 uses stride 136)
    __shared__ float sh2[128];
    __shared__ float sh3[256];
    __shared__ float tot[2 * 256];

    const int n   = blockIdx.x;
    const int tid = threadIdx.x;

    // ---- scales / weight folds / input tile ----
    if (tid < 64) {
        float a1 = g1[tid] * rsqrtf(v1[tid] + BN_EPS);
        sh1[tid] = a1 * (b1[tid] - m1[tid]) + be1[tid];
    }
    if (tid < 128) {
        float a2 = g2[tid] * rsqrtf(v2[tid] + BN_EPS);
        sh2[tid] = a2 * (b2[tid] - m2[tid]) + be2[tid];
    }
    {
        float a3 = g3[tid] * rsqrtf(v3[tid] + BN_EPS);
        sh3[tid] = a3 * (b3[tid] - m3[tid]) + be3[tid];
    }
    for (int i = tid; i < 64 * 18; i += 256) {
        int co = i / 18;
        float a = g1[co] * rsqrtf(v1[co] + BN_EPS);
        w1f[i] = a * w1[i];
    }
    for (int i = tid; i < 768; i += 256) {
        int t = i / 6, c = i - t * 6;
        xs[c * 130 + 1 + t] = x[n * 768 + i];
    }
    if (tid < 6)   { xs[tid * 130] = 0.f; xs[tid * 130 + 129] = 0.f; }
    if (tid < 64)  { h1s[tid * 136] = 0.f; h1s[tid * 136 + 129] = 0.f; }
    if (tid < 128) { h2s[tid * 136] = 0.f; h2s[tid * 136 + 129] = 0.f; }
    __syncthreads();

    // ---- conv1 + BN + lrelu -> h1s (tf32-rounded) ----
    #pragma unroll 4
    for (int r = 0; r < 32; ++r) {
        int idx = tid + 256 * r;
        int co = idx >> 7, t = idx & 127;
        float v = sh1[co];
        #pragma unroll
        for (int ci = 0; ci < 6; ++ci)
            #pragma unroll
            for (int k = 0; k < 3; ++k)
                v += w1f[co * 18 + ci * 3 + k] * xs[ci * 130 + t + k];
        h1s[co * 136 + 1 + t] = tf32r(lrelu(v));
    }

    const int lane = tid & 31, warp = tid >> 5;
    const int wm = warp >> 1;            // 0..3
    const int wn = warp & 1;             // 0..1
    const int gid = lane >> 2, tig = lane & 3;

    // ================== conv2: M=128 co, N=128 t, K=192 ==================
    {
        float d2[2][8][4];
        #pragma unroll
        for (int mt = 0; mt < 2; ++mt)
            #pragma unroll
            for (int nt = 0; nt < 8; ++nt)
                #pragma unroll
                for (int q = 0; q < 4; ++q) d2[mt][nt][q] = 0.f;

        for (int kc = 0; kc < 12; ++kc) {
            __syncthreads();
            // coalesced staging: 16 rows x 32 float4
            #pragma unroll
            for (int i = tid; i < 512; i += 256) {
                int row = i >> 5, c4 = i & 31;
                float4 v = *(const float4*)&g_w2t[(kc * 16 + row) * 128 + c4 * 4];
                *(float4*)&ws[row * 136 + c4 * 4] = v;
            }
            __syncthreads();
            #pragma unroll
            for (int ks = 0; ks < 2; ++ks) {
                int k0  = kc * 16 + ks * 8;
                int tap = k0 >> 6, cib = k0 & 63;
                const float* wr0 = &ws[(ks * 8 + tig) * 136];
                const float* wr4 = &ws[(ks * 8 + tig + 4) * 136];
                uint32_t a[2][4];
                #pragma unroll
                for (int mt = 0; mt < 2; ++mt) {
                    int m = wm * 32 + mt * 16 + gid;
                    a[mt][0] = fbits(wr0[m]);     a[mt][1] = fbits(wr0[m + 8]);
                    a[mt][2] = fbits(wr4[m]);     a[mt][3] = fbits(wr4[m + 8]);
                }
                const float* h0 = &h1s[(cib + tig) * 136 + tap];
                const float* h4 = &h1s[(cib + tig + 4) * 136 + tap];
                #pragma unroll
                for (int nt = 0; nt < 8; ++nt) {
                    int nn = wn * 64 + nt * 8 + gid;
                    uint32_t b0 = fbits(h0[nn]);
                    uint32_t b1 = fbits(h4[nn]);
                    mma8(d2[0][nt], a[0], b0, b1);
                    mma8(d2[1][nt], a[1], b0, b1);
                }
            }
        }

        // epilogue: shift + lrelu + tf32-round -> h2s (smem, +1 halo offset)
        __syncthreads();
        #pragma unroll
        for (int mt = 0; mt < 2; ++mt) {
            int r0 = wm * 32 + mt * 16 + gid;
            int r1 = r0 + 8;
            float s0 = sh2[r0], s1 = sh2[r1];
            #pragma unroll
            for (int nt = 0; nt < 8; ++nt) {
                int t = wn * 64 + nt * 8 + tig * 2;
                h2s[r0 * 136 + 1 + t] = tf32r(lrelu(d2[mt][nt][0] + s0));
                h2s[r0 * 136 + 2 + t] = tf32r(lrelu(d2[mt][nt][1] + s0));
                h2s[r1 * 136 + 1 + t] = tf32r(lrelu(d2[mt][nt][2] + s1));
                h2s[r1 * 136 + 2 + t] = tf32r(lrelu(d2[mt][nt][3] + s1));
            }
        }
    }

    // ================== conv3: M=256 co, N=128 t, K=384 ==================
    float d3[4][8][4];
    #pragma unroll
    for (int mt = 0; mt < 4; ++mt)
        #pragma unroll
        for (int nt = 0; nt < 8; ++nt)
            #pragma unroll
            for (int q = 0; q < 4; ++q) d3[mt][nt][q] = 0.f;

    for (int kc = 0; kc < 24; ++kc) {
        __syncthreads();
        // coalesced staging: 16 rows x 64 float4
        #pragma unroll
        for (int i = tid; i < 1024; i += 256) {
            int row = i >> 6, c4 = i & 63;
            float4 v = *(const float4*)&g_w3t[(kc * 16 + row) * 256 + c4 * 4];
            *(float4*)&ws[row * 264 + c4 * 4] = v;
        }
        __syncthreads();
        #pragma unroll
        for (int ks = 0; ks < 2; ++ks) {
            int k0  = kc * 16 + ks * 8;
            int tap = k0 >> 7, cib = k0 & 127;
            const float* wr0 = &ws[(ks * 8 + tig) * 264];
            const float* wr4 = &ws[(ks * 8 + tig + 4) * 264];
            uint32_t a[4][4];
            #pragma unroll
            for (int mt = 0; mt < 4; ++mt) {
                int m = wm * 64 + mt * 16 + gid;
                a[mt][0] = fbits(wr0[m]);     a[mt][1] = fbits(wr0[m + 8]);
                a[mt][2] = fbits(wr4[m]);     a[mt][3] = fbits(wr4[m + 8]);
            }
            const float* h0 = &h2s[(cib + tig) * 136 + tap];
            const float* h4 = &h2s[(cib + tig + 4) * 136 + tap];
            #pragma unroll
            for (int nt = 0; nt < 8; ++nt) {
                int nn = wn * 64 + nt * 8 + gid;
                uint32_t b0 = fbits(h0[nn]);
                uint32_t b1 = fbits(h4[nn]);
                #pragma unroll
                for (int mt = 0; mt < 4; ++mt)
                    mma8(d3[mt][nt], a[mt], b0, b1);
            }
        }
    }

    // ---- epilogue: shift + lrelu + pools ----
    float* msn = g_ms + (long)n * 3328;
    #pragma unroll
    for (int mt = 0; mt < 4; ++mt) {
        int cl0 = wm * 64 + mt * 16 + gid;   // co 0..255
        int cl1 = cl0 + 8;
        float s0 = sh3[cl0], s1 = sh3[cl1];
        float p0[4] = {0.f, 0.f, 0.f, 0.f};
        float p1[4] = {0.f, 0.f, 0.f, 0.f};
        #pragma unroll
        for (int nt = 0; nt < 8; ++nt) {
            int u = nt >> 1;
            p0[u] += lrelu(d3[mt][nt][0] + s0) + lrelu(d3[mt][nt][1] + s0);
            p1[u] += lrelu(d3[mt][nt][2] + s1) + lrelu(d3[mt][nt][3] + s1);
        }
        #pragma unroll
        for (int u = 0; u < 4; ++u) {
            p0[u] += __shfl_xor_sync(0xffffffffu, p0[u], 1);
            p0[u] += __shfl_xor_sync(0xffffffffu, p0[u], 2);
            p1[u] += __shfl_xor_sync(0xffffffffu, p1[u], 1);
            p1[u] += __shfl_xor_sync(0xffffffffu, p1[u], 2);
        }
        if (tig == 0) {
            #pragma unroll
            for (int u = 0; u < 4; ++u) {
                msn[cl0 * 8 + wn * 4 + u] = p0[u] * (1.f / 16.f);
                msn[cl1 * 8 + wn * 4 + u] = p1[u] * (1.f / 16.f);
            }
            msn[2048 + cl0 * 4 + wn * 2 + 0] = (p0[0] + p0[1]) * (1.f / 32.f);
            msn[2048 + cl0 * 4 + wn * 2 + 1] = (p0[2] + p0[3]) * (1.f / 32.f);
            msn[2048 + cl1 * 4 + wn * 2 + 0] = (p1[0] + p1[1]) * (1.f / 32.f);
            msn[2048 + cl1 * 4 + wn * 2 + 1] = (p1[2] + p1[3]) * (1.f / 32.f);
            tot[wn * 256 + cl0] = p0[0] + p0[1] + p0[2] + p0[3];
            tot[wn * 256 + cl1] = p1[0] + p1[1] + p1[2] + p1[3];
        }
    }
    __syncthreads();
    msn[3072 + tid] = (tot[tid] + tot[256 + tid]) * (1.f / 128.f);
}

// ============================================================================
// FC kernel (tf32 mma, double-buffered smem, register prefetch).
// C[M][Nc] = act(A[M][K] * B[Nc][K]^T + bias), 64x64 tile, 256 threads.
// ============================================================================
template <int K, int Nc, bool RELU>
__global__ __launch_bounds__(256) void fc_mma_kernel(
    const float* __restrict__ A, const float* __restrict__ B,
    const float* __restrict__ bias, float* __restrict__ C)
{
    __shared__ float As[2][16 * 72];   // [k][m], stride 72
    __shared__ float Bs[2][16 * 72];

    const int tid = threadIdx.x;
    const int m0 = blockIdx.y * 64, n0 = blockIdx.x * 64;
    const int lane = tid & 31, warp = tid >> 5;
    const int wm = warp >> 2, wn = warp & 3;
    const int gid = lane >> 2, tig = lane & 3;
    const int row = tid >> 2, q = tid & 3;   // staging: 64 rows x 4 k-quads

    const float* Ap = &A[(long)(m0 + row) * K + q * 4];
    const float* Bp = &B[(long)(n0 + row) * K + q * 4];

    float d[2][2][4];
    #pragma unroll
    for (int mt = 0; mt < 2; ++mt)
        #pragma unroll
        for (int nt = 0; nt < 2; ++nt)
            #pragma unroll
            for (int qq = 0; qq < 4; ++qq) d[mt][nt][qq] = 0.f;

    float4 av = *(const float4*)Ap;
    float4 bv = *(const float4*)Bp;
    {
        As[0][(q * 4 + 0) * 72 + row] = tf32r(av.x);
        As[0][(q * 4 + 1) * 72 + row] = tf32r(av.y);
        As[0][(q * 4 + 2) * 72 + row] = tf32r(av.z);
        As[0][(q * 4 + 3) * 72 + row] = tf32r(av.w);
        Bs[0][(q * 4 + 0) * 72 + row] = tf32r(bv.x);
        Bs[0][(q * 4 + 1) * 72 + row] = tf32r(bv.y);
        Bs[0][(q * 4 + 2) * 72 + row] = tf32r(bv.z);
        Bs[0][(q * 4 + 3) * 72 + row] = tf32r(bv.w);
    }
    __syncthreads();

    const int NC = K / 16;
    for (int kc = 0; kc < NC; ++kc) {
        int p = kc & 1;
        if (kc + 1 < NC) {
            av = *(const float4*)(Ap + (kc + 1) * 16);
            bv = *(const float4*)(Bp + (kc + 1) * 16);
        }
        #pragma unroll
        for (int ks = 0; ks < 2; ++ks) {
            const float* ar0 = &As[p][(ks * 8 + tig) * 72];
            const float* ar4 = &As[p][(ks * 8 + tig + 4) * 72];
            const float* br0 = &Bs[p][(ks * 8 + tig) * 72];
            const float* br4 = &Bs[p][(ks * 8 + tig + 4) * 72];
            uint32_t a[2][4];
            #pragma unroll
            for (int mt = 0; mt < 2; ++mt) {
                int m = wm * 32 + mt * 16 + gid;
                a[mt][0] = fbits(ar0[m]);  a[mt][1] = fbits(ar0[m + 8]);
                a[mt][2] = fbits(ar4[m]);  a[mt][3] = fbits(ar4[m + 8]);
            }
            #pragma unroll
            for (int nt = 0; nt < 2; ++nt) {
                int nn = wn * 16 + nt * 8 + gid;
                uint32_t b0 = fbits(br0[nn]);
                uint32_t b1 = fbits(br4[nn]);
                mma8(d[0][nt], a[0], b0, b1);
                mma8(d[1][nt], a[1], b0, b1);
            }
        }
        if (kc + 1 < NC) {
            int pn = p ^ 1;
            As[pn][(q * 4 + 0) * 72 + row] = tf32r(av.x);
            As[pn][(q * 4 + 1) * 72 + row] = tf32r(av.y);
            As[pn][(q * 4 + 2) * 72 + row] = tf32r(av.z);
            As[pn][(q * 4 + 3) * 72 + row] = tf32r(av.w);
            Bs[pn][(q * 4 + 0) * 72 + row] = tf32r(bv.x);
            Bs[pn][(q * 4 + 1) * 72 + row] = tf32r(bv.y);
            Bs[pn][(q * 4 + 2) * 72 + row] = tf32r(bv.z);
            Bs[pn][(q * 4 + 3) * 72 + row] = tf32r(bv.w);
        }
        __syncthreads();
    }

    // epilogue
    #pragma unroll
    for (int mt = 0; mt < 2; ++mt) {
        int r0 = m0 + wm * 32 + mt * 16 + gid;
        int r1 = r0 + 8;
        #pragma unroll
        for (int nt = 0; nt < 2; ++nt) {
            int nn = n0 + wn * 16 + nt * 8 + tig * 2;
            float bb0 = bias[nn], bb1 = bias[nn + 1];
            float o0 = d[mt][nt][0] + bb0, o1 = d[mt][nt][1] + bb1;
            float o2 = d[mt][nt][2] + bb0, o3 = d[mt][nt][3] + bb1;
            if (RELU) {
                o0 = fmaxf(o0, 0.f); o1 = fmaxf(o1, 0.f);
                o2 = fmaxf(o2, 0.f); o3 = fmaxf(o3, 0.f);
            }
            float2 v0 = { o0, o1 }, v1 = { o2, o3 };
            *(float2*)&C[(long)r0 * Nc + nn] = v0;
            *(float2*)&C[(long)r1 * Nc + nn] = v1;
        }
    }
}

// ============================================================================
// metadata.txt / setup_inputs() dict order:
//   0:x 1:w1 2:b1 3:w2 4:b2 5:w3 6:b3
//   7:g1 8:be1 9:m1 10:v1  11:g2 12:be2 13:m2 14:v2  15:g3 16:be3 17:m3 18:v3
//   19:lw1 20:lb1 21:lw2 22:lb2
// ============================================================================
extern "C" void kernel_launch(void* const* d_in, const int* in_sizes, int n_in,
                              void* d_out, int out_size)
{
    const float* x   = (const float*)d_in[0];
    const float* w1  = (const float*)d_in[1];
    const float* b1  = (const float*)d_in[2];
    const float* w2  = (const float*)d_in[3];
    const float* b2  = (const float*)d_in[4];
    const float* w3  = (const float*)d_in[5];
    const float* b3  = (const float*)d_in[6];
    const float* g1  = (const float*)d_in[7];
    const float* be1 = (const float*)d_in[8];
    const float* m1  = (const float*)d_in[9];
    const float* v1  = (const float*)d_in[10];
    const float* g2  = (const float*)d_in[11];
    const float* be2 = (const float*)d_in[12];
    const float* m2  = (const float*)d_in[13];
    const float* v2  = (const float*)d_in[14];
    const float* g3  = (const float*)d_in[15];
    const float* be3 = (const float*)d_in[16];
    const float* m3  = (const float*)d_in[17];
    const float* v3  = (const float*)d_in[18];
    const float* lw1 = (const float*)d_in[19];
    const float* lb1 = (const float*)d_in[20];
    const float* lw2 = (const float*)d_in[21];
    const float* lb2 = (const float*)d_in[22];
    float* out = (float*)d_out;

    const int fused_dyn = (64 * 136 + 128 * 136) * sizeof(float);  // 104448
    cudaFuncSetAttribute(fused_conv_kernel,
                         cudaFuncAttributeMaxDynamicSharedMemorySize, fused_dyn);

    prep_weights_kernel<<<384, 256>>>(w2, g2, v2, w3, g3, v3);

    fused_conv_kernel<<<1024, 256, fused_dyn>>>(
        x, w1, b1, g1, be1, m1, v1,
        b2, g2, be2, m2, v2,
        b3, g3, be3, m3, v3);

    float* fc1o;
    float* msp;
    cudaGetSymbolAddress((void**)&msp,  g_ms);
    cudaGetSymbolAddress((void**)&fc1o, g_fc1);

    fc_mma_kernel<3328, 512, true><<<dim3(8, 16), 256>>>(msp, lw1, lb1, fc1o);
    fc_mma_kernel<512, 256, false><<<dim3(4, 16), 256>>>(fc1o, lw2, lb2, out);
}

// round 8
// speedup vs baseline: 3.3066x; 1.0412x over previous
#include <cuda_runtime.h>
#include <cuda_bf16.h>
#include <math.h>
#include <stdint.h>

#define BN_EPS 1e-5f
#define SLOPE 0.1f

// -------- scratch (device globals; no allocation allowed) --------
__device__ float g_ms[1024 * 3328];        // pooled features
__device__ float g_fc1[1024 * 512];        // fc1 output
__device__ float g_w2t[192 * 128];         // conv2 weights: BN-folded, tf32, [kabs][co]
__device__ float g_w3t[384 * 256];         // conv3 weights: BN-folded, tf32, [kabs][co]

// ---- helpers ----
__device__ __forceinline__ float tf32r(float x) {
    uint32_t u;
    asm("cvt.rna.tf32.f32 %0, %1;" : "=r"(u) : "f"(x));
    return __uint_as_float(u);
}
__device__ __forceinline__ uint32_t fbits(float x) { return __float_as_uint(x); }

__device__ __forceinline__ void mma8(float* d, const uint32_t* a, uint32_t b0, uint32_t b1) {
    asm volatile(
        "mma.sync.aligned.m16n8k8.row.col.f32.tf32.tf32.f32 "
        "{%0,%1,%2,%3}, {%4,%5,%6,%7}, {%8,%9}, {%0,%1,%2,%3};"
        : "+f"(d[0]), "+f"(d[1]), "+f"(d[2]), "+f"(d[3])
        : "r"(a[0]), "r"(a[1]), "r"(a[2]), "r"(a[3]), "r"(b0), "r"(b1));
}
__device__ __forceinline__ float lrelu(float v) { return v > 0.f ? v : SLOPE * v; }

// ============================================================================
// Prep kernel: fold BN scale into w2/w3, tf32-round, transpose to [kabs][co].
// ============================================================================
__global__ __launch_bounds__(256) void prep_weights_kernel(
    const float* __restrict__ w2, const float* __restrict__ g2, const float* __restrict__ v2,
    const float* __restrict__ w3, const float* __restrict__ g3, const float* __restrict__ v3)
{
    int i = blockIdx.x * 256 + threadIdx.x;
    if (i < 192 * 128) {
        int kabs = i >> 7, co = i & 127;
        int tap = kabs >> 6, ci = kabs & 63;
        float a = g2[co] * rsqrtf(v2[co] + BN_EPS);
        g_w2t[i] = tf32r(a * w2[co * 192 + ci * 3 + tap]);
    }
    if (i < 384 * 256) {
        int kabs = i >> 8, co = i & 255;
        int tap = kabs >> 7, ci = kabs & 127;
        float a = g3[co] * rsqrtf(v3[co] + BN_EPS);
        g_w3t[i] = tf32r(a * w3[co * 384 + ci * 3 + tap]);
    }
}

// ============================================================================
// FUSED kernel: conv1 (fp32) -> conv2 (tf32 mma) -> conv3 (tf32 mma) -> pools.
// grid = 1024 (one block per n), 512 threads = 16 warps as 4(M) x 4(N).
//   conv2: M=128, N=128, K=192.  warp tile 32co x 32t.  d2[2][4][4].
//   conv3: M=256, N=128, K=384.  warp tile 64co x 32t.  d3[4][4][4].
// Weight staging double-buffered (register prefetch, 1 sync per K-chunk).
// ============================================================================
extern __shared__ float dsm[];

__global__ __launch_bounds__(512) void fused_conv_kernel(
    const float* __restrict__ x,
    const float* __restrict__ w1, const float* __restrict__ b1,
    const float* __restrict__ g1, const float* __restrict__ be1,
    const float* __restrict__ m1, const float* __restrict__ v1,
    const float* __restrict__ b2,
    const float* __restrict__ g2, const float* __restrict__ be2,
    const float* __restrict__ m2, const float* __restrict__ v2,
    const float* __restrict__ b3,
    const float* __restrict__ g3, const float* __restrict__ be3,
    const float* __restrict__ m3, const float* __restrict__ v3)
{
    float* h1s = dsm;                 // [64][136], valid t at 1..128, halo zeros
    float* h2s = dsm + 64 * 136;      // [128][136]
    __shared__ float xs[6 * 130];
    __shared__ float w1f[64 * 18];
    __shared__ float sh1[64];
    __shared__ float ws[2][16 * 264]; // double-buffered weight chunks
    __shared__ float sh2[128];
    __shared__ float sh3[256];
    __shared__ float tot[4 * 256];

    const int n   = blockIdx.x;
    const int tid = threadIdx.x;

    // ---- scales / weight folds / input tile ----
    if (tid < 64) {
        float a1 = g1[tid] * rsqrtf(v1[tid] + BN_EPS);
        sh1[tid] = a1 * (b1[tid] - m1[tid]) + be1[tid];
    }
    if (tid < 128) {
        float a2 = g2[tid] * rsqrtf(v2[tid] + BN_EPS);
        sh2[tid] = a2 * (b2[tid] - m2[tid]) + be2[tid];
    }
    if (tid < 256) {
        float a3 = g3[tid] * rsqrtf(v3[tid] + BN_EPS);
        sh3[tid] = a3 * (b3[tid] - m3[tid]) + be3[tid];
    }
    for (int i = tid; i < 64 * 18; i += 512) {
        int co = i / 18;
        float a = g1[co] * rsqrtf(v1[co] + BN_EPS);
        w1f[i] = a * w1[i];
    }
    for (int i = tid; i < 768; i += 512) {
        int t = i / 6, c = i - t * 6;
        xs[c * 130 + 1 + t] = x[n * 768 + i];
    }
    if (tid < 6)   { xs[tid * 130] = 0.f; xs[tid * 130 + 129] = 0.f; }
    if (tid < 64)  { h1s[tid * 136] = 0.f; h1s[tid * 136 + 129] = 0.f; }
    if (tid < 128) { h2s[tid * 136] = 0.f; h2s[tid * 136 + 129] = 0.f; }
    __syncthreads();

    // ---- conv1 + BN + lrelu -> h1s (tf32-rounded) ----
    #pragma unroll 4
    for (int r = 0; r < 16; ++r) {
        int idx = tid + 512 * r;
        int co = idx >> 7, t = idx & 127;
        float v = sh1[co];
        #pragma unroll
        for (int ci = 0; ci < 6; ++ci)
            #pragma unroll
            for (int k = 0; k < 3; ++k)
                v += w1f[co * 18 + ci * 3 + k] * xs[ci * 130 + t + k];
        h1s[co * 136 + 1 + t] = tf32r(lrelu(v));
    }

    const int lane = tid & 31, warp = tid >> 5;
    const int wm = warp >> 2;            // 0..3
    const int wn = warp & 3;             // 0..3
    const int gid = lane >> 2, tig = lane & 3;

    // ================== conv2: warp tile 32co x 32t ==================
    {
        const int srow = tid >> 5, sc4 = tid & 31;   // staging map: 16 rows x 32 float4
        float d2[2][4][4];
        #pragma unroll
        for (int mt = 0; mt < 2; ++mt)
            #pragma unroll
            for (int nt = 0; nt < 4; ++nt)
                #pragma unroll
                for (int q = 0; q < 4; ++q) d2[mt][nt][q] = 0.f;

        // preload chunk 0
        float4 pv = *(const float4*)&g_w2t[srow * 128 + sc4 * 4];
        *(float4*)&ws[0][srow * 136 + sc4 * 4] = pv;
        __syncthreads();

        for (int kc = 0; kc < 12; ++kc) {
            int p = kc & 1;
            if (kc < 11)
                pv = *(const float4*)&g_w2t[((kc + 1) * 16 + srow) * 128 + sc4 * 4];
            #pragma unroll
            for (int ks = 0; ks < 2; ++ks) {
                int k0  = kc * 16 + ks * 8;
                int tap = k0 >> 6, cib = k0 & 63;
                const float* wr0 = &ws[p][(ks * 8 + tig) * 136];
                const float* wr4 = &ws[p][(ks * 8 + tig + 4) * 136];
                uint32_t a[2][4];
                #pragma unroll
                for (int mt = 0; mt < 2; ++mt) {
                    int m = wm * 32 + mt * 16 + gid;
                    a[mt][0] = fbits(wr0[m]);     a[mt][1] = fbits(wr0[m + 8]);
                    a[mt][2] = fbits(wr4[m]);     a[mt][3] = fbits(wr4[m + 8]);
                }
                const float* h0 = &h1s[(cib + tig) * 136 + tap];
                const float* h4 = &h1s[(cib + tig + 4) * 136 + tap];
                #pragma unroll
                for (int nt = 0; nt < 4; ++nt) {
                    int nn = wn * 32 + nt * 8 + gid;
                    uint32_t b0 = fbits(h0[nn]);
                    uint32_t b1 = fbits(h4[nn]);
                    mma8(d2[0][nt], a[0], b0, b1);
                    mma8(d2[1][nt], a[1], b0, b1);
                }
            }
            if (kc < 11)
                *(float4*)&ws[p ^ 1][srow * 136 + sc4 * 4] = pv;
            __syncthreads();
        }

        // epilogue: shift + lrelu + tf32-round -> h2s
        #pragma unroll
        for (int mt = 0; mt < 2; ++mt) {
            int r0 = wm * 32 + mt * 16 + gid;
            int r1 = r0 + 8;
            float s0 = sh2[r0], s1 = sh2[r1];
            #pragma unroll
            for (int nt = 0; nt < 4; ++nt) {
                int t = wn * 32 + nt * 8 + tig * 2;
                h2s[r0 * 136 + 1 + t] = tf32r(lrelu(d2[mt][nt][0] + s0));
                h2s[r0 * 136 + 2 + t] = tf32r(lrelu(d2[mt][nt][1] + s0));
                h2s[r1 * 136 + 1 + t] = tf32r(lrelu(d2[mt][nt][2] + s1));
                h2s[r1 * 136 + 2 + t] = tf32r(lrelu(d2[mt][nt][3] + s1));
            }
        }
    }

    // ================== conv3: warp tile 64co x 32t ==================
    float d3[4][4][4];
    #pragma unroll
    for (int mt = 0; mt < 4; ++mt)
        #pragma unroll
        for (int nt = 0; nt < 4; ++nt)
            #pragma unroll
            for (int q = 0; q < 4; ++q) d3[mt][nt][q] = 0.f;

    {
        // staging map: 16 rows x 64 float4, 2 items per thread
        const int r0s = tid >> 6, c0s = tid & 63;
        const int r1s = (tid + 512) >> 6, c1s = tid & 63;
        float4 pv0 = *(const float4*)&g_w3t[r0s * 256 + c0s * 4];
        float4 pv1 = *(const float4*)&g_w3t[r1s * 256 + c1s * 4];
        // write into ws[0] (conv2's last mma used ws[1]; write-only here, sync below)
        *(float4*)&ws[0][r0s * 264 + c0s * 4] = pv0;
        *(float4*)&ws[0][r1s * 264 + c1s * 4] = pv1;
        __syncthreads();   // covers h2s epilogue writes + ws[0] staging

        for (int kc = 0; kc < 24; ++kc) {
            int p = kc & 1;
            if (kc < 23) {
                pv0 = *(const float4*)&g_w3t[((kc + 1) * 16 + r0s) * 256 + c0s * 4];
                pv1 = *(const float4*)&g_w3t[((kc + 1) * 16 + r1s) * 256 + c1s * 4];
            }
            #pragma unroll
            for (int ks = 0; ks < 2; ++ks) {
                int k0  = kc * 16 + ks * 8;
                int tap = k0 >> 7, cib = k0 & 127;
                const float* wr0 = &ws[p][(ks * 8 + tig) * 264];
                const float* wr4 = &ws[p][(ks * 8 + tig + 4) * 264];
                uint32_t a[4][4];
                #pragma unroll
                for (int mt = 0; mt < 4; ++mt) {
                    int m = wm * 64 + mt * 16 + gid;
                    a[mt][0] = fbits(wr0[m]);     a[mt][1] = fbits(wr0[m + 8]);
                    a[mt][2] = fbits(wr4[m]);     a[mt][3] = fbits(wr4[m + 8]);
                }
                const float* h0 = &h2s[(cib + tig) * 136 + tap];
                const float* h4 = &h2s[(cib + tig + 4) * 136 + tap];
                #pragma unroll
                for (int nt = 0; nt < 4; ++nt) {
                    int nn = wn * 32 + nt * 8 + gid;
                    uint32_t b0 = fbits(h0[nn]);
                    uint32_t b1 = fbits(h4[nn]);
                    #pragma unroll
                    for (int mt = 0; mt < 4; ++mt)
                        mma8(d3[mt][nt], a[mt], b0, b1);
                }
            }
            if (kc < 23) {
                *(float4*)&ws[p ^ 1][r0s * 264 + c0s * 4] = pv0;
                *(float4*)&ws[p ^ 1][r1s * 264 + c1s * 4] = pv1;
            }
            __syncthreads();
        }
    }

    // ---- epilogue: shift + lrelu + pools ----
    // t = wn*32 + nt*8 + tig*2 + {0,1}.  local bin = 2*wn + nt/2; mid bin = wn.
    float* msn = g_ms + (long)n * 3328;
    #pragma unroll
    for (int mt = 0; mt < 4; ++mt) {
        int cl0 = wm * 64 + mt * 16 + gid;   // co 0..255
        int cl1 = cl0 + 8;
        float s0 = sh3[cl0], s1 = sh3[cl1];
        float p0[2] = {0.f, 0.f};
        float p1[2] = {0.f, 0.f};
        #pragma unroll
        for (int nt = 0; nt < 4; ++nt) {
            int u = nt >> 1;
            p0[u] += lrelu(d3[mt][nt][0] + s0) + lrelu(d3[mt][nt][1] + s0);
            p1[u] += lrelu(d3[mt][nt][2] + s1) + lrelu(d3[mt][nt][3] + s1);
        }
        #pragma unroll
        for (int u = 0; u < 2; ++u) {
            p0[u] += __shfl_xor_sync(0xffffffffu, p0[u], 1);
            p0[u] += __shfl_xor_sync(0xffffffffu, p0[u], 2);
            p1[u] += __shfl_xor_sync(0xffffffffu, p1[u], 1);
            p1[u] += __shfl_xor_sync(0xffffffffu, p1[u], 2);
        }
        if (tig == 0) {
            #pragma unroll
            for (int u = 0; u < 2; ++u) {
                msn[cl0 * 8 + 2 * wn + u] = p0[u] * (1.f / 16.f);
                msn[cl1 * 8 + 2 * wn + u] = p1[u] * (1.f / 16.f);
            }
            msn[2048 + cl0 * 4 + wn] = (p0[0] + p0[1]) * (1.f / 32.f);
            msn[2048 + cl1 * 4 + wn] = (p1[0] + p1[1]) * (1.f / 32.f);
            tot[wn * 256 + cl0] = p0[0] + p0[1];
            tot[wn * 256 + cl1] = p1[0] + p1[1];
        }
    }
    __syncthreads();
    if (tid < 256) {
        float g = tot[tid] + tot[256 + tid] + tot[512 + tid] + tot[768 + tid];
        msn[3072 + tid] = g * (1.f / 128.f);
    }
}

// ============================================================================
// FC kernel (tf32 mma, double-buffered smem, register prefetch).
// C[M][Nc] = act(A[M][K] * B[Nc][K]^T + bias), 64x64 tile, 256 threads.
// ============================================================================
template <int K, int Nc, bool RELU>
__global__ __launch_bounds__(256) void fc_mma_kernel(
    const float* __restrict__ A, const float* __restrict__ B,
    const float* __restrict__ bias, float* __restrict__ C)
{
    __shared__ float As[2][16 * 72];   // [k][m], stride 72
    __shared__ float Bs[2][16 * 72];

    const int tid = threadIdx.x;
    const int m0 = blockIdx.y * 64, n0 = blockIdx.x * 64;
    const int lane = tid & 31, warp = tid >> 5;
    const int wm = warp >> 2, wn = warp & 3;
    const int gid = lane >> 2, tig = lane & 3;
    const int row = tid >> 2, q = tid & 3;   // staging: 64 rows x 4 k-quads

    const float* Ap = &A[(long)(m0 + row) * K + q * 4];
    const float* Bp = &B[(long)(n0 + row) * K + q * 4];

    float d[2][2][4];
    #pragma unroll
    for (int mt = 0; mt < 2; ++mt)
        #pragma unroll
        for (int nt = 0; nt < 2; ++nt)
            #pragma unroll
            for (int qq = 0; qq < 4; ++qq) d[mt][nt][qq] = 0.f;

    float4 av = *(const float4*)Ap;
    float4 bv = *(const float4*)Bp;
    {
        As[0][(q * 4 + 0) * 72 + row] = tf32r(av.x);
        As[0][(q * 4 + 1) * 72 + row] = tf32r(av.y);
        As[0][(q * 4 + 2) * 72 + row] = tf32r(av.z);
        As[0][(q * 4 + 3) * 72 + row] = tf32r(av.w);
        Bs[0][(q * 4 + 0) * 72 + row] = tf32r(bv.x);
        Bs[0][(q * 4 + 1) * 72 + row] = tf32r(bv.y);
        Bs[0][(q * 4 + 2) * 72 + row] = tf32r(bv.z);
        Bs[0][(q * 4 + 3) * 72 + row] = tf32r(bv.w);
    }
    __syncthreads();

    const int NC = K / 16;
    for (int kc = 0; kc < NC; ++kc) {
        int p = kc & 1;
        if (kc + 1 < NC) {
            av = *(const float4*)(Ap + (kc + 1) * 16);
            bv = *(const float4*)(Bp + (kc + 1) * 16);
        }
        #pragma unroll
        for (int ks = 0; ks < 2; ++ks) {
            const float* ar0 = &As[p][(ks * 8 + tig) * 72];
            const float* ar4 = &As[p][(ks * 8 + tig + 4) * 72];
            const float* br0 = &Bs[p][(ks * 8 + tig) * 72];
            const float* br4 = &Bs[p][(ks * 8 + tig + 4) * 72];
            uint32_t a[2][4];
            #pragma unroll
            for (int mt = 0; mt < 2; ++mt) {
                int m = wm * 32 + mt * 16 + gid;
                a[mt][0] = fbits(ar0[m]);  a[mt][1] = fbits(ar0[m + 8]);
                a[mt][2] = fbits(ar4[m]);  a[mt][3] = fbits(ar4[m + 8]);
            }
            #pragma unroll
            for (int nt = 0; nt < 2; ++nt) {
                int nn = wn * 16 + nt * 8 + gid;
                uint32_t b0 = fbits(br0[nn]);
                uint32_t b1 = fbits(br4[nn]);
                mma8(d[0][nt], a[0], b0, b1);
                mma8(d[1][nt], a[1], b0, b1);
            }
        }
        if (kc + 1 < NC) {
            int pn = p ^ 1;
            As[pn][(q * 4 + 0) * 72 + row] = tf32r(av.x);
            As[pn][(q * 4 + 1) * 72 + row] = tf32r(av.y);
            As[pn][(q * 4 + 2) * 72 + row] = tf32r(av.z);
            As[pn][(q * 4 + 3) * 72 + row] = tf32r(av.w);
            Bs[pn][(q * 4 + 0) * 72 + row] = tf32r(bv.x);
            Bs[pn][(q * 4 + 1) * 72 + row] = tf32r(bv.y);
            Bs[pn][(q * 4 + 2) * 72 + row] = tf32r(bv.z);
            Bs[pn][(q * 4 + 3) * 72 + row] = tf32r(bv.w);
        }
        __syncthreads();
    }

    // epilogue
    #pragma unroll
    for (int mt = 0; mt < 2; ++mt) {
        int r0 = m0 + wm * 32 + mt * 16 + gid;
        int r1 = r0 + 8;
        #pragma unroll
        for (int nt = 0; nt < 2; ++nt) {
            int nn = n0 + wn * 16 + nt * 8 + tig * 2;
            float bb0 = bias[nn], bb1 = bias[nn + 1];
            float o0 = d[mt][nt][0] + bb0, o1 = d[mt][nt][1] + bb1;
            float o2 = d[mt][nt][2] + bb0, o3 = d[mt][nt][3] + bb1;
            if (RELU) {
                o0 = fmaxf(o0, 0.f); o1 = fmaxf(o1, 0.f);
                o2 = fmaxf(o2, 0.f); o3 = fmaxf(o3, 0.f);
            }
            float2 v0 = { o0, o1 }, v1 = { o2, o3 };
            *(float2*)&C[(long)r0 * Nc + nn] = v0;
            *(float2*)&C[(long)r1 * Nc + nn] = v1;
        }
    }
}

// ============================================================================
// metadata.txt / setup_inputs() dict order:
//   0:x 1:w1 2:b1 3:w2 4:b2 5:w3 6:b3
//   7:g1 8:be1 9:m1 10:v1  11:g2 12:be2 13:m2 14:v2  15:g3 16:be3 17:m3 18:v3
//   19:lw1 20:lb1 21:lw2 22:lb2
// ============================================================================
extern "C" void kernel_launch(void* const* d_in, const int* in_sizes, int n_in,
                              void* d_out, int out_size)
{
    const float* x   = (const float*)d_in[0];
    const float* w1  = (const float*)d_in[1];
    const float* b1  = (const float*)d_in[2];
    const float* w2  = (const float*)d_in[3];
    const float* b2  = (const float*)d_in[4];
    const float* w3  = (const float*)d_in[5];
    const float* b3  = (const float*)d_in[6];
    const float* g1  = (const float*)d_in[7];
    const float* be1 = (const float*)d_in[8];
    const float* m1  = (const float*)d_in[9];
    const float* v1  = (const float*)d_in[10];
    const float* g2  = (const float*)d_in[11];
    const float* be2 = (const float*)d_in[12];
    const float* m2  = (const float*)d_in[13];
    const float* v2  = (const float*)d_in[14];
    const float* g3  = (const float*)d_in[15];
    const float* be3 = (const float*)d_in[16];
    const float* m3  = (const float*)d_in[17];
    const float* v3  = (const float*)d_in[18];
    const float* lw1 = (const float*)d_in[19];
    const float* lb1 = (const float*)d_in[20];
    const float* lw2 = (const float*)d_in[21];
    const float* lb2 = (const float*)d_in[22];
    float* out = (float*)d_out;

    const int fused_dyn = (64 * 136 + 128 * 136) * sizeof(float);  // 104448
    cudaFuncSetAttribute(fused_conv_kernel,
                         cudaFuncAttributeMaxDynamicSharedMemorySize, fused_dyn);

    prep_weights_kernel<<<384, 256>>>(w2, g2, v2, w3, g3, v3);

    fused_conv_kernel<<<1024, 512, fused_dyn>>>(
        x, w1, b1, g1, be1, m1, v1,
        b2, g2, be2, m2, v2,
        b3, g3, be3, m3, v3);

    float* fc1o;
    float* msp;
    cudaGetSymbolAddress((void**)&msp,  g_ms);
    cudaGetSymbolAddress((void**)&fc1o, g_fc1);

    fc_mma_kernel<3328, 512, true><<<dim3(8, 16), 256>>>(msp, lw1, lb1, fc1o);
    fc_mma_kernel<512, 256, false><<<dim3(4, 16), 256>>>(fc1o, lw2, lb2, out);
}

// round 9
// speedup vs baseline: 3.4132x; 1.0322x over previous
#include <cuda_runtime.h>
#include <cuda_bf16.h>
#include <math.h>
#include <stdint.h>

#define BN_EPS 1e-5f
#define SLOPE 0.1f

// -------- scratch (device globals; no allocation allowed) --------
__device__ float g_ms[1024 * 3328];        // pooled features
__device__ float g_fc1[1024 * 512];        // fc1 output
// fragment-major weights: [kg][cog][lane][4], kg = k-group of 8, cog = co-group of 16
__device__ float g_w2f[24 * 8 * 32 * 4];   // conv2 (K=192 -> 24 kg, 128 co -> 8 cog)
__device__ float g_w3f[48 * 16 * 32 * 4];  // conv3 (K=384 -> 48 kg, 256 co -> 16 cog)

// ---- helpers ----
__device__ __forceinline__ float tf32r(float x) {
    uint32_t u;
    asm("cvt.rna.tf32.f32 %0, %1;" : "=r"(u) : "f"(x));
    return __uint_as_float(u);
}
__device__ __forceinline__ uint32_t fbits(float x) { return __float_as_uint(x); }

__device__ __forceinline__ void mma8(float* d, const uint32_t* a, uint32_t b0, uint32_t b1) {
    asm volatile(
        "mma.sync.aligned.m16n8k8.row.col.f32.tf32.tf32.f32 "
        "{%0,%1,%2,%3}, {%4,%5,%6,%7}, {%8,%9}, {%0,%1,%2,%3};"
        : "+f"(d[0]), "+f"(d[1]), "+f"(d[2]), "+f"(d[3])
        : "r"(a[0]), "r"(a[1]), "r"(a[2]), "r"(a[3]), "r"(b0), "r"(b1));
}
__device__ __forceinline__ float lrelu(float v) { return v > 0.f ? v : SLOPE * v; }

// ============================================================================
// Prep kernel: fold BN scale, tf32-round, and lay out weights in per-lane
// mma-fragment order so the main kernel loads each A fragment with 1 LDS.128.
// Fragment order per lane (gid=lane>>2, tig=lane&3):
//   f0 = W[k=tig ][co=gid]   f1 = W[k=tig ][co=gid+8]
//   f2 = W[k=tig+4][co=gid]  f3 = W[k=tig+4][co=gid+8]
// (k relative to kg*8, co relative to cog*16; tap-major k = tap*C + ci)
// ============================================================================
__global__ __launch_bounds__(256) void prep_weights_kernel(
    const float* __restrict__ w2, const float* __restrict__ g2, const float* __restrict__ v2,
    const float* __restrict__ w3, const float* __restrict__ g3, const float* __restrict__ v3)
{
    int i = blockIdx.x * 256 + threadIdx.x;   // up to 98304
    // conv2: 24 kg x 8 cog x 32 lane x 4
    if (i < 24576) {
        int f = i & 3, lane = (i >> 2) & 31, cog = (i >> 7) & 7, kg = i >> 10;
        int gid = lane >> 2, tig = lane & 3;
        int k  = kg * 8 + tig + ((f & 2) ? 4 : 0);
        int co = cog * 16 + gid + ((f & 1) ? 8 : 0);
        int tap = k >> 6, ci = k & 63;
        float a = g2[co] * rsqrtf(v2[co] + BN_EPS);
        g_w2f[i] = tf32r(a * w2[co * 192 + ci * 3 + tap]);
    }
    // conv3: 48 kg x 16 cog x 32 lane x 4
    if (i < 98304) {
        int f = i & 3, lane = (i >> 2) & 31, cog = (i >> 7) & 15, kg = i >> 11;
        int gid = lane >> 2, tig = lane & 3;
        int k  = kg * 8 + tig + ((f & 2) ? 4 : 0);
        int co = cog * 16 + gid + ((f & 1) ? 8 : 0);
        int tap = k >> 7, ci = k & 127;
        float a = g3[co] * rsqrtf(v3[co] + BN_EPS);
        g_w3f[i] = tf32r(a * w3[co * 384 + ci * 3 + tap]);
    }
}

// ============================================================================
// FUSED kernel: conv1 (fp32) -> conv2 (tf32 mma) -> conv3 (tf32 mma) -> pools.
// grid = 1024 (one block per n), 512 threads = 16 warps as 4(M) x 4(N).
//   conv2: warp tile 32co x 32t.  conv3: warp tile 64co x 32t.
// A fragments: single LDS.128 from fragment-major ws.  B: scalar LDS from
// h1s/h2s (stride 136 = 8 mod 32 -> conflict-free).
// Weight staging double-buffered (register prefetch, 1 sync per 16-K chunk).
// ============================================================================
extern __shared__ float dsm[];

__global__ __launch_bounds__(512) void fused_conv_kernel(
    const float* __restrict__ x,
    const float* __restrict__ w1, const float* __restrict__ b1,
    const float* __restrict__ g1, const float* __restrict__ be1,
    const float* __restrict__ m1, const float* __restrict__ v1,
    const float* __restrict__ b2,
    const float* __restrict__ g2, const float* __restrict__ be2,
    const float* __restrict__ m2, const float* __restrict__ v2,
    const float* __restrict__ b3,
    const float* __restrict__ g3, const float* __restrict__ be3,
    const float* __restrict__ m3, const float* __restrict__ v3)
{
    float* h1s = dsm;                 // [64][136], valid t at 1..128, halo zeros
    float* h2s = dsm + 64 * 136;      // [128][136]
    __shared__ float xs[6 * 130];
    __shared__ float w1f[64 * 18];
    __shared__ float sh1[64];
    __shared__ float ws[2][4096];     // double-buffered fragment-major weight chunks
    __shared__ float sh2[128];
    __shared__ float sh3[256];
    __shared__ float tot[4 * 256];

    const int n   = blockIdx.x;
    const int tid = threadIdx.x;

    // ---- scales / weight folds / input tile ----
    if (tid < 64) {
        float a1 = g1[tid] * rsqrtf(v1[tid] + BN_EPS);
        sh1[tid] = a1 * (b1[tid] - m1[tid]) + be1[tid];
    }
    if (tid < 128) {
        float a2 = g2[tid] * rsqrtf(v2[tid] + BN_EPS);
        sh2[tid] = a2 * (b2[tid] - m2[tid]) + be2[tid];
    }
    if (tid < 256) {
        float a3 = g3[tid] * rsqrtf(v3[tid] + BN_EPS);
        sh3[tid] = a3 * (b3[tid] - m3[tid]) + be3[tid];
    }
    for (int i = tid; i < 64 * 18; i += 512) {
        int co = i / 18;
        float a = g1[co] * rsqrtf(v1[co] + BN_EPS);
        w1f[i] = a * w1[i];
    }
    for (int i = tid; i < 768; i += 512) {
        int t = i / 6, c = i - t * 6;
        xs[c * 130 + 1 + t] = x[n * 768 + i];
    }
    if (tid < 6)   { xs[tid * 130] = 0.f; xs[tid * 130 + 129] = 0.f; }
    if (tid < 64)  { h1s[tid * 136] = 0.f; h1s[tid * 136 + 129] = 0.f; }
    if (tid < 128) { h2s[tid * 136] = 0.f; h2s[tid * 136 + 129] = 0.f; }
    __syncthreads();

    // ---- conv1 + BN + lrelu -> h1s (tf32-rounded) ----
    #pragma unroll 4
    for (int r = 0; r < 16; ++r) {
        int idx = tid + 512 * r;
        int co = idx >> 7, t = idx & 127;
        float v = sh1[co];
        #pragma unroll
        for (int ci = 0; ci < 6; ++ci)
            #pragma unroll
            for (int k = 0; k < 3; ++k)
                v += w1f[co * 18 + ci * 3 + k] * xs[ci * 130 + t + k];
        h1s[co * 136 + 1 + t] = tf32r(lrelu(v));
    }

    const int lane = tid & 31, warp = tid >> 5;
    const int wm = warp >> 2;            // 0..3
    const int wn = warp & 3;             // 0..3
    const int gid = lane >> 2, tig = lane & 3;

    // ================== conv2: warp tile 32co x 32t ==================
    {
        float d2[2][4][4];
        #pragma unroll
        for (int mt = 0; mt < 2; ++mt)
            #pragma unroll
            for (int nt = 0; nt < 4; ++nt)
                #pragma unroll
                for (int q = 0; q < 4; ++q) d2[mt][nt][q] = 0.f;

        // chunk = 2 kgroups = 2048 floats; one float4 per thread
        float4 pv = *(const float4*)&g_w2f[tid * 4];
        *(float4*)&ws[0][tid * 4] = pv;
        __syncthreads();

        for (int kc = 0; kc < 12; ++kc) {
            int p = kc & 1;
            if (kc < 11)
                pv = *(const float4*)&g_w2f[(kc + 1) * 2048 + tid * 4];
            #pragma unroll
            for (int ks = 0; ks < 2; ++ks) {
                int k0  = kc * 16 + ks * 8;
                int tap = k0 >> 6, cib = k0 & 63;
                uint32_t a[2][4];
                #pragma unroll
                for (int mt = 0; mt < 2; ++mt) {
                    float4 af = *(const float4*)&ws[p][ks * 1024 + (wm * 2 + mt) * 128 + lane * 4];
                    a[mt][0] = fbits(af.x); a[mt][1] = fbits(af.y);
                    a[mt][2] = fbits(af.z); a[mt][3] = fbits(af.w);
                }
                const float* h0 = &h1s[(cib + tig) * 136 + tap];
                const float* h4 = &h1s[(cib + tig + 4) * 136 + tap];
                #pragma unroll
                for (int nt = 0; nt < 4; ++nt) {
                    int nn = wn * 32 + nt * 8 + gid;
                    uint32_t b0 = fbits(h0[nn]);
                    uint32_t b1 = fbits(h4[nn]);
                    mma8(d2[0][nt], a[0], b0, b1);
                    mma8(d2[1][nt], a[1], b0, b1);
                }
            }
            if (kc < 11)
                *(float4*)&ws[p ^ 1][tid * 4] = pv;
            __syncthreads();
        }

        // epilogue: shift + lrelu + tf32-round -> h2s
        #pragma unroll
        for (int mt = 0; mt < 2; ++mt) {
            int r0 = wm * 32 + mt * 16 + gid;
            int r1 = r0 + 8;
            float s0 = sh2[r0], s1 = sh2[r1];
            #pragma unroll
            for (int nt = 0; nt < 4; ++nt) {
                int t = wn * 32 + nt * 8 + tig * 2;
                h2s[r0 * 136 + 1 + t] = tf32r(lrelu(d2[mt][nt][0] + s0));
                h2s[r0 * 136 + 2 + t] = tf32r(lrelu(d2[mt][nt][1] + s0));
                h2s[r1 * 136 + 1 + t] = tf32r(lrelu(d2[mt][nt][2] + s1));
                h2s[r1 * 136 + 2 + t] = tf32r(lrelu(d2[mt][nt][3] + s1));
            }
        }
    }

    // ================== conv3: warp tile 64co x 32t ==================
    float d3[4][4][4];
    #pragma unroll
    for (int mt = 0; mt < 4; ++mt)
        #pragma unroll
        for (int nt = 0; nt < 4; ++nt)
            #pragma unroll
            for (int q = 0; q < 4; ++q) d3[mt][nt][q] = 0.f;

    {
        // chunk = 2 kgroups = 4096 floats; two float4 per thread
        float4 pv0 = *(const float4*)&g_w3f[tid * 4];
        float4 pv1 = *(const float4*)&g_w3f[2048 + tid * 4];
        *(float4*)&ws[0][tid * 4]        = pv0;
        *(float4*)&ws[0][2048 + tid * 4] = pv1;
        __syncthreads();   // covers h2s epilogue writes + ws[0] staging

        for (int kc = 0; kc < 24; ++kc) {
            int p = kc & 1;
            if (kc < 23) {
                pv0 = *(const float4*)&g_w3f[(kc + 1) * 4096 + tid * 4];
                pv1 = *(const float4*)&g_w3f[(kc + 1) * 4096 + 2048 + tid * 4];
            }
            #pragma unroll
            for (int ks = 0; ks < 2; ++ks) {
                int k0  = kc * 16 + ks * 8;
                int tap = k0 >> 7, cib = k0 & 127;
                uint32_t a[4][4];
                #pragma unroll
                for (int mt = 0; mt < 4; ++mt) {
                    float4 af = *(const float4*)&ws[p][ks * 2048 + (wm * 4 + mt) * 128 + lane * 4];
                    a[mt][0] = fbits(af.x); a[mt][1] = fbits(af.y);
                    a[mt][2] = fbits(af.z); a[mt][3] = fbits(af.w);
                }
                const float* h0 = &h2s[(cib + tig) * 136 + tap];
                const float* h4 = &h2s[(cib + tig + 4) * 136 + tap];
                #pragma unroll
                for (int nt = 0; nt < 4; ++nt) {
                    int nn = wn * 32 + nt * 8 + gid;
                    uint32_t b0 = fbits(h0[nn]);
                    uint32_t b1 = fbits(h4[nn]);
                    #pragma unroll
                    for (int mt = 0; mt < 4; ++mt)
                        mma8(d3[mt][nt], a[mt], b0, b1);
                }
            }
            if (kc < 23) {
                *(float4*)&ws[p ^ 1][tid * 4]        = pv0;
                *(float4*)&ws[p ^ 1][2048 + tid * 4] = pv1;
            }
            __syncthreads();
        }
    }

    // ---- epilogue: shift + lrelu + pools ----
    // t = wn*32 + nt*8 + tig*2 + {0,1}.  local bin = 2*wn + nt/2; mid bin = wn.
    float* msn = g_ms + (long)n * 3328;
    #pragma unroll
    for (int mt = 0; mt < 4; ++mt) {
        int cl0 = wm * 64 + mt * 16 + gid;   // co 0..255
        int cl1 = cl0 + 8;
        float s0 = sh3[cl0], s1 = sh3[cl1];
        float p0[2] = {0.f, 0.f};
        float p1[2] = {0.f, 0.f};
        #pragma unroll
        for (int nt = 0; nt < 4; ++nt) {
            int u = nt >> 1;
            p0[u] += lrelu(d3[mt][nt][0] + s0) + lrelu(d3[mt][nt][1] + s0);
            p1[u] += lrelu(d3[mt][nt][2] + s1) + lrelu(d3[mt][nt][3] + s1);
        }
        #pragma unroll
        for (int u = 0; u < 2; ++u) {
            p0[u] += __shfl_xor_sync(0xffffffffu, p0[u], 1);
            p0[u] += __shfl_xor_sync(0xffffffffu, p0[u], 2);
            p1[u] += __shfl_xor_sync(0xffffffffu, p1[u], 1);
            p1[u] += __shfl_xor_sync(0xffffffffu, p1[u], 2);
        }
        if (tig == 0) {
            #pragma unroll
            for (int u = 0; u < 2; ++u) {
                msn[cl0 * 8 + 2 * wn + u] = p0[u] * (1.f / 16.f);
                msn[cl1 * 8 + 2 * wn + u] = p1[u] * (1.f / 16.f);
            }
            msn[2048 + cl0 * 4 + wn] = (p0[0] + p0[1]) * (1.f / 32.f);
            msn[2048 + cl1 * 4 + wn] = (p1[0] + p1[1]) * (1.f / 32.f);
            tot[wn * 256 + cl0] = p0[0] + p0[1];
            tot[wn * 256 + cl1] = p1[0] + p1[1];
        }
    }
    __syncthreads();
    if (tid < 256) {
        float g = tot[tid] + tot[256 + tid] + tot[512 + tid] + tot[768 + tid];
        msn[3072 + tid] = g * (1.f / 128.f);
    }
}

// ============================================================================
// FC kernel (tf32 mma, double-buffered smem, register prefetch).
// C[M][Nc] = act(A[M][K] * B[Nc][K]^T + bias), 64x64 tile, 256 threads.
// ============================================================================
template <int K, int Nc, bool RELU>
__global__ __launch_bounds__(256) void fc_mma_kernel(
    const float* __restrict__ A, const float* __restrict__ B,
    const float* __restrict__ bias, float* __restrict__ C)
{
    __shared__ float As[2][16 * 72];   // [k][m], stride 72
    __shared__ float Bs[2][16 * 72];

    const int tid = threadIdx.x;
    const int m0 = blockIdx.y * 64, n0 = blockIdx.x * 64;
    const int lane = tid & 31, warp = tid >> 5;
    const int wm = warp >> 2, wn = warp & 3;
    const int gid = lane >> 2, tig = lane & 3;
    const int row = tid >> 2, q = tid & 3;   // staging: 64 rows x 4 k-quads

    const float* Ap = &A[(long)(m0 + row) * K + q * 4];
    const float* Bp = &B[(long)(n0 + row) * K + q * 4];

    float d[2][2][4];
    #pragma unroll
    for (int mt = 0; mt < 2; ++mt)
        #pragma unroll
        for (int nt = 0; nt < 2; ++nt)
            #pragma unroll
            for (int qq = 0; qq < 4; ++qq) d[mt][nt][qq] = 0.f;

    float4 av = *(const float4*)Ap;
    float4 bv = *(const float4*)Bp;
    {
        As[0][(q * 4 + 0) * 72 + row] = tf32r(av.x);
        As[0][(q * 4 + 1) * 72 + row] = tf32r(av.y);
        As[0][(q * 4 + 2) * 72 + row] = tf32r(av.z);
        As[0][(q * 4 + 3) * 72 + row] = tf32r(av.w);
        Bs[0][(q * 4 + 0) * 72 + row] = tf32r(bv.x);
        Bs[0][(q * 4 + 1) * 72 + row] = tf32r(bv.y);
        Bs[0][(q * 4 + 2) * 72 + row] = tf32r(bv.z);
        Bs[0][(q * 4 + 3) * 72 + row] = tf32r(bv.w);
    }
    __syncthreads();

    const int NC = K / 16;
    for (int kc = 0; kc < NC; ++kc) {
        int p = kc & 1;
        if (kc + 1 < NC) {
            av = *(const float4*)(Ap + (kc + 1) * 16);
            bv = *(const float4*)(Bp + (kc + 1) * 16);
        }
        #pragma unroll
        for (int ks = 0; ks < 2; ++ks) {
            const float* ar0 = &As[p][(ks * 8 + tig) * 72];
            const float* ar4 = &As[p][(ks * 8 + tig + 4) * 72];
            const float* br0 = &Bs[p][(ks * 8 + tig) * 72];
            const float* br4 = &Bs[p][(ks * 8 + tig + 4) * 72];
            uint32_t a[2][4];
            #pragma unroll
            for (int mt = 0; mt < 2; ++mt) {
                int m = wm * 32 + mt * 16 + gid;
                a[mt][0] = fbits(ar0[m]);  a[mt][1] = fbits(ar0[m + 8]);
                a[mt][2] = fbits(ar4[m]);  a[mt][3] = fbits(ar4[m + 8]);
            }
            #pragma unroll
            for (int nt = 0; nt < 2; ++nt) {
                int nn = wn * 16 + nt * 8 + gid;
                uint32_t b0 = fbits(br0[nn]);
                uint32_t b1 = fbits(br4[nn]);
                mma8(d[0][nt], a[0], b0, b1);
                mma8(d[1][nt], a[1], b0, b1);
            }
        }
        if (kc + 1 < NC) {
            int pn = p ^ 1;
            As[pn][(q * 4 + 0) * 72 + row] = tf32r(av.x);
            As[pn][(q * 4 + 1) * 72 + row] = tf32r(av.y);
            As[pn][(q * 4 + 2) * 72 + row] = tf32r(av.z);
            As[pn][(q * 4 + 3) * 72 + row] = tf32r(av.w);
            Bs[pn][(q * 4 + 0) * 72 + row] = tf32r(bv.x);
            Bs[pn][(q * 4 + 1) * 72 + row] = tf32r(bv.y);
            Bs[pn][(q * 4 + 2) * 72 + row] = tf32r(bv.z);
            Bs[pn][(q * 4 + 3) * 72 + row] = tf32r(bv.w);
        }
        __syncthreads();
    }

    // epilogue
    #pragma unroll
    for (int mt = 0; mt < 2; ++mt) {
        int r0 = m0 + wm * 32 + mt * 16 + gid;
        int r1 = r0 + 8;
        #pragma unroll
        for (int nt = 0; nt < 2; ++nt) {
            int nn = n0 + wn * 16 + nt * 8 + tig * 2;
            float bb0 = bias[nn], bb1 = bias[nn + 1];
            float o0 = d[mt][nt][0] + bb0, o1 = d[mt][nt][1] + bb1;
            float o2 = d[mt][nt][2] + bb0, o3 = d[mt][nt][3] + bb1;
            if (RELU) {
                o0 = fmaxf(o0, 0.f); o1 = fmaxf(o1, 0.f);
                o2 = fmaxf(o2, 0.f); o3 = fmaxf(o3, 0.f);
            }
            float2 v0 = { o0, o1 }, v1 = { o2, o3 };
            *(float2*)&C[(long)r0 * Nc + nn] = v0;
            *(float2*)&C[(long)r1 * Nc + nn] = v1;
        }
    }
}

// ============================================================================
// metadata.txt / setup_inputs() dict order:
//   0:x 1:w1 2:b1 3:w2 4:b2 5:w3 6:b3
//   7:g1 8:be1 9:m1 10:v1  11:g2 12:be2 13:m2 14:v2  15:g3 16:be3 17:m3 18:v3
//   19:lw1 20:lb1 21:lw2 22:lb2
// ============================================================================
extern "C" void kernel_launch(void* const* d_in, const int* in_sizes, int n_in,
                              void* d_out, int out_size)
{
    const float* x   = (const float*)d_in[0];
    const float* w1  = (const float*)d_in[1];
    const float* b1  = (const float*)d_in[2];
    const float* w2  = (const float*)d_in[3];
    const float* b2  = (const float*)d_in[4];
    const float* w3  = (const float*)d_in[5];
    const float* b3  = (const float*)d_in[6];
    const float* g1  = (const float*)d_in[7];
    const float* be1 = (const float*)d_in[8];
    const float* m1  = (const float*)d_in[9];
    const float* v1  = (const float*)d_in[10];
    const float* g2  = (const float*)d_in[11];
    const float* be2 = (const float*)d_in[12];
    const float* m2  = (const float*)d_in[13];
    const float* v2  = (const float*)d_in[14];
    const float* g3  = (const float*)d_in[15];
    const float* be3 = (const float*)d_in[16];
    const float* m3  = (const float*)d_in[17];
    const float* v3  = (const float*)d_in[18];
    const float* lw1 = (const float*)d_in[19];
    const float* lb1 = (const float*)d_in[20];
    const float* lw2 = (const float*)d_in[21];
    const float* lb2 = (const float*)d_in[22];
    float* out = (float*)d_out;

    const int fused_dyn = (64 * 136 + 128 * 136) * sizeof(float);  // 104448
    cudaFuncSetAttribute(fused_conv_kernel,
                         cudaFuncAttributeMaxDynamicSharedMemorySize, fused_dyn);

    prep_weights_kernel<<<384, 256>>>(w2, g2, v2, w3, g3, v3);

    fused_conv_kernel<<<1024, 512, fused_dyn>>>(
        x, w1, b1, g1, be1, m1, v1,
        b2, g2, be2, m2, v2,
        b3, g3, be3, m3, v3);

    float* fc1o;
    float* msp;
    cudaGetSymbolAddress((void**)&msp,  g_ms);
    cudaGetSymbolAddress((void**)&fc1o, g_fc1);

    fc_mma_kernel<3328, 512, true><<<dim3(8, 16), 256>>>(msp, lw1, lb1, fc1o);
    fc_mma_kernel<512, 256, false><<<dim3(4, 16), 256>>>(fc1o, lw2, lb2, out);
}

// round 11
// speedup vs baseline: 3.5536x; 1.0411x over previous
#include <cuda_runtime.h>
#include <cuda_bf16.h>
#include <math.h>
#include <stdint.h>

#define BN_EPS 1e-5f
#define SLOPE 0.1f

// -------- scratch (device globals; no allocation allowed) --------
__device__ float g_ms[1024 * 3328];        // pooled features
__device__ float g_fc1[1024 * 512];        // fc1 output
// fragment-major weights: [kg][cog][lane][4], kg = k-group of 8, cog = co-group of 16
__device__ float g_w2f[24 * 8 * 32 * 4];   // conv2 (K=192 -> 24 kg, 128 co -> 8 cog)
__device__ float g_w3f[48 * 16 * 32 * 4];  // conv3 (K=384 -> 48 kg, 256 co -> 16 cog)

// ---- helpers ----
__device__ __forceinline__ float tf32r(float x) {
    uint32_t u;
    asm("cvt.rna.tf32.f32 %0, %1;" : "=r"(u) : "f"(x));
    return __uint_as_float(u);
}
__device__ __forceinline__ uint32_t fbits(float x) { return __float_as_uint(x); }

__device__ __forceinline__ void mma8(float* d, const uint32_t* a, uint32_t b0, uint32_t b1) {
    asm volatile(
        "mma.sync.aligned.m16n8k8.row.col.f32.tf32.tf32.f32 "
        "{%0,%1,%2,%3}, {%4,%5,%6,%7}, {%8,%9}, {%0,%1,%2,%3};"
        : "+f"(d[0]), "+f"(d[1]), "+f"(d[2]), "+f"(d[3])
        : "r"(a[0]), "r"(a[1]), "r"(a[2]), "r"(a[3]), "r"(b0), "r"(b1));
}
__device__ __forceinline__ float lrelu(float v) { return v > 0.f ? v : SLOPE * v; }

// ============================================================================
// Prep kernel: fold BN scale, tf32-round, lay out weights in per-lane
// mma-fragment order (1 LDS.128 per A fragment in the main kernel).
//   f0 = W[k=tig ][co=gid]   f1 = W[k=tig ][co=gid+8]
//   f2 = W[k=tig+4][co=gid]  f3 = W[k=tig+4][co=gid+8]
// ============================================================================
__global__ __launch_bounds__(256) void prep_weights_kernel(
    const float* __restrict__ w2, const float* __restrict__ g2, const float* __restrict__ v2,
    const float* __restrict__ w3, const float* __restrict__ g3, const float* __restrict__ v3)
{
    int i = blockIdx.x * 256 + threadIdx.x;   // up to 98304
    if (i < 24576) {      // conv2: 24 kg x 8 cog x 32 lane x 4
        int f = i & 3, lane = (i >> 2) & 31, cog = (i >> 7) & 7, kg = i >> 10;
        int gid = lane >> 2, tig = lane & 3;
        int k  = kg * 8 + tig + ((f & 2) ? 4 : 0);
        int co = cog * 16 + gid + ((f & 1) ? 8 : 0);
        int tap = k >> 6, ci = k & 63;
        float a = g2[co] * rsqrtf(v2[co] + BN_EPS);
        g_w2f[i] = tf32r(a * w2[co * 192 + ci * 3 + tap]);
    }
    if (i < 98304) {      // conv3: 48 kg x 16 cog x 32 lane x 4
        int f = i & 3, lane = (i >> 2) & 31, cog = (i >> 7) & 15, kg = i >> 11;
        int gid = lane >> 2, tig = lane & 3;
        int k  = kg * 8 + tig + ((f & 2) ? 4 : 0);
        int co = cog * 16 + gid + ((f & 1) ? 8 : 0);
        int tap = k >> 7, ci = k & 127;
        float a = g3[co] * rsqrtf(v3[co] + BN_EPS);
        g_w3f[i] = tf32r(a * w3[co * 384 + ci * 3 + tap]);
    }
}

// ============================================================================
// FUSED kernel: conv1 (fp32) -> conv2 (tf32 mma) -> conv3 (tf32 mma) -> pools.
// grid = 1024 (one block per n), 256 threads = 8 warps as 4(M) x 2(N).
//   conv2: warp tile 32co x 64t.  d2[2][8][4].
//   conv3: warp tile 64co x 64t.  d3[4][8][4].   (128 B smem traffic per mma)
// A fragments: single LDS.128 from fragment-major ws.  B: scalar LDS from
// h1s/h2s (stride 136 = 8 mod 32 -> conflict-free).
// Weight staging double-buffered (register prefetch, 1 sync per 16-K chunk).
// ============================================================================
extern __shared__ float dsm[];

__global__ __launch_bounds__(256) void fused_conv_kernel(
    const float* __restrict__ x,
    const float* __restrict__ w1, const float* __restrict__ b1,
    const float* __restrict__ g1, const float* __restrict__ be1,
    const float* __restrict__ m1, const float* __restrict__ v1,
    const float* __restrict__ b2,
    const float* __restrict__ g2, const float* __restrict__ be2,
    const float* __restrict__ m2, const float* __restrict__ v2,
    const float* __restrict__ b3,
    const float* __restrict__ g3, const float* __restrict__ be3,
    const float* __restrict__ m3, const float* __restrict__ v3)
{
    float* h1s = dsm;                 // [64][136], valid t at 1..128, halo zeros
    float* h2s = dsm + 64 * 136;      // [128][136]
    __shared__ float xs[6 * 130];
    __shared__ float w1f[64 * 18];
    __shared__ float sh1[64];
    __shared__ float ws[2][4096];     // double-buffered fragment-major weight chunks
    __shared__ float sh2[128];
    __shared__ float sh3[256];
    __shared__ float tot[2 * 256];

    const int n   = blockIdx.x;
    const int tid = threadIdx.x;

    // ---- scales / weight folds / input tile ----
    if (tid < 64) {
        float a1 = g1[tid] * rsqrtf(v1[tid] + BN_EPS);
        sh1[tid] = a1 * (b1[tid] - m1[tid]) + be1[tid];
    }
    if (tid < 128) {
        float a2 = g2[tid] * rsqrtf(v2[tid] + BN_EPS);
        sh2[tid] = a2 * (b2[tid] - m2[tid]) + be2[tid];
    }
    {
        float a3 = g3[tid] * rsqrtf(v3[tid] + BN_EPS);
        sh3[tid] = a3 * (b3[tid] - m3[tid]) + be3[tid];
    }
    for (int i = tid; i < 64 * 18; i += 256) {
        int co = i / 18;
        float a = g1[co] * rsqrtf(v1[co] + BN_EPS);
        w1f[i] = a * w1[i];
    }
    for (int i = tid; i < 768; i += 256) {
        int t = i / 6, c = i - t * 6;
        xs[c * 130 + 1 + t] = x[n * 768 + i];
    }
    if (tid < 6)   { xs[tid * 130] = 0.f; xs[tid * 130 + 129] = 0.f; }
    if (tid < 64)  { h1s[tid * 136] = 0.f; h1s[tid * 136 + 129] = 0.f; }
    if (tid < 128) { h2s[tid * 136] = 0.f; h2s[tid * 136 + 129] = 0.f; }
    __syncthreads();

    // ---- conv1 + BN + lrelu -> h1s (tf32-rounded) ----
    #pragma unroll 4
    for (int r = 0; r < 32; ++r) {
        int idx = tid + 256 * r;
        int co = idx >> 7, t = idx & 127;
        float v = sh1[co];
        #pragma unroll
        for (int ci = 0; ci < 6; ++ci)
            #pragma unroll
            for (int k = 0; k < 3; ++k)
                v += w1f[co * 18 + ci * 3 + k] * xs[ci * 130 + t + k];
        h1s[co * 136 + 1 + t] = tf32r(lrelu(v));
    }

    const int lane = tid & 31, warp = tid >> 5;
    const int wm = warp >> 1;            // 0..3
    const int wn = warp & 1;             // 0..1
    const int gid = lane >> 2, tig = lane & 3;

    // ================== conv2: warp tile 32co x 64t ==================
    {
        float d2[2][8][4];
        #pragma unroll
        for (int mt = 0; mt < 2; ++mt)
            #pragma unroll
            for (int nt = 0; nt < 8; ++nt)
                #pragma unroll
                for (int q = 0; q < 4; ++q) d2[mt][nt][q] = 0.f;

        // chunk = 16 K = 2 kgroups = 2048 floats; 2 float4 per thread
        float4 pva = *(const float4*)&g_w2f[tid * 4];
        float4 pvb = *(const float4*)&g_w2f[1024 + tid * 4];
        *(float4*)&ws[0][tid * 4]        = pva;
        *(float4*)&ws[0][1024 + tid * 4] = pvb;
        __syncthreads();

        for (int kc = 0; kc < 12; ++kc) {
            int p = kc & 1;
            if (kc < 11) {
                pva = *(const float4*)&g_w2f[(kc + 1) * 2048 + tid * 4];
                pvb = *(const float4*)&g_w2f[(kc + 1) * 2048 + 1024 + tid * 4];
            }
            #pragma unroll
            for (int ks = 0; ks < 2; ++ks) {
                int k0  = kc * 16 + ks * 8;
                int tap = k0 >> 6, cib = k0 & 63;
                uint32_t a[2][4];
                #pragma unroll
                for (int mt = 0; mt < 2; ++mt) {
                    float4 af = *(const float4*)&ws[p][ks * 1024 + (wm * 2 + mt) * 128 + lane * 4];
                    a[mt][0] = fbits(af.x); a[mt][1] = fbits(af.y);
                    a[mt][2] = fbits(af.z); a[mt][3] = fbits(af.w);
                }
                const float* h0 = &h1s[(cib + tig) * 136 + tap];
                const float* h4 = &h1s[(cib + tig + 4) * 136 + tap];
                #pragma unroll
                for (int nt = 0; nt < 8; ++nt) {
                    int nn = wn * 64 + nt * 8 + gid;
                    uint32_t b0 = fbits(h0[nn]);
                    uint32_t b1 = fbits(h4[nn]);
                    mma8(d2[0][nt], a[0], b0, b1);
                    mma8(d2[1][nt], a[1], b0, b1);
                }
            }
            if (kc < 11) {
                *(float4*)&ws[p ^ 1][tid * 4]        = pva;
                *(float4*)&ws[p ^ 1][1024 + tid * 4] = pvb;
            }
            __syncthreads();
        }

        // epilogue: shift + lrelu + tf32-round -> h2s
        #pragma unroll
        for (int mt = 0; mt < 2; ++mt) {
            int r0 = wm * 32 + mt * 16 + gid;
            int r1 = r0 + 8;
            float s0 = sh2[r0], s1 = sh2[r1];
            #pragma unroll
            for (int nt = 0; nt < 8; ++nt) {
                int t = wn * 64 + nt * 8 + tig * 2;
                h2s[r0 * 136 + 1 + t] = tf32r(lrelu(d2[mt][nt][0] + s0));
                h2s[r0 * 136 + 2 + t] = tf32r(lrelu(d2[mt][nt][1] + s0));
                h2s[r1 * 136 + 1 + t] = tf32r(lrelu(d2[mt][nt][2] + s1));
                h2s[r1 * 136 + 2 + t] = tf32r(lrelu(d2[mt][nt][3] + s1));
            }
        }
    }

    // ================== conv3: warp tile 64co x 64t ==================
    float d3[4][8][4];
    #pragma unroll
    for (int mt = 0; mt < 4; ++mt)
        #pragma unroll
        for (int nt = 0; nt < 8; ++nt)
            #pragma unroll
            for (int q = 0; q < 4; ++q) d3[mt][nt][q] = 0.f;

    {
        // chunk = 16 K = 2 kgroups = 4096 floats; 4 float4 per thread
        float4 pv0 = *(const float4*)&g_w3f[tid * 4];
        float4 pv1 = *(const float4*)&g_w3f[1024 + tid * 4];
        float4 pv2 = *(const float4*)&g_w3f[2048 + tid * 4];
        float4 pv3 = *(const float4*)&g_w3f[3072 + tid * 4];
        *(float4*)&ws[0][tid * 4]        = pv0;
        *(float4*)&ws[0][1024 + tid * 4] = pv1;
        *(float4*)&ws[0][2048 + tid * 4] = pv2;
        *(float4*)&ws[0][3072 + tid * 4] = pv3;
        __syncthreads();   // covers h2s epilogue writes + ws[0] staging

        for (int kc = 0; kc < 24; ++kc) {
            int p = kc & 1;
            if (kc < 23) {
                pv0 = *(const float4*)&g_w3f[(kc + 1) * 4096 + tid * 4];
                pv1 = *(const float4*)&g_w3f[(kc + 1) * 4096 + 1024 + tid * 4];
                pv2 = *(const float4*)&g_w3f[(kc + 1) * 4096 + 2048 + tid * 4];
                pv3 = *(const float4*)&g_w3f[(kc + 1) * 4096 + 3072 + tid * 4];
            }
            #pragma unroll
            for (int ks = 0; ks < 2; ++ks) {
                int k0  = kc * 16 + ks * 8;
                int tap = k0 >> 7, cib = k0 & 127;
                uint32_t a[4][4];
                #pragma unroll
                for (int mt = 0; mt < 4; ++mt) {
                    float4 af = *(const float4*)&ws[p][ks * 2048 + (wm * 4 + mt) * 128 + lane * 4];
                    a[mt][0] = fbits(af.x); a[mt][1] = fbits(af.y);
                    a[mt][2] = fbits(af.z); a[mt][3] = fbits(af.w);
                }
                const float* h0 = &h2s[(cib + tig) * 136 + tap];
                const float* h4 = &h2s[(cib + tig + 4) * 136 + tap];
                #pragma unroll
                for (int nt = 0; nt < 8; ++nt) {
                    int nn = wn * 64 + nt * 8 + gid;
                    uint32_t b0 = fbits(h0[nn]);
                    uint32_t b1 = fbits(h4[nn]);
                    #pragma unroll
                    for (int mt = 0; mt < 4; ++mt)
                        mma8(d3[mt][nt], a[mt], b0, b1);
                }
            }
            if (kc < 23) {
                *(float4*)&ws[p ^ 1][tid * 4]        = pv0;
                *(float4*)&ws[p ^ 1][1024 + tid * 4] = pv1;
                *(float4*)&ws[p ^ 1][2048 + tid * 4] = pv2;
                *(float4*)&ws[p ^ 1][3072 + tid * 4] = pv3;
            }
            __syncthreads();
        }
    }

    // ---- epilogue: shift + lrelu + pools ----
    // t = wn*64 + nt*8 + tig*2 + {0,1}.  local bin = wn*4 + nt/2; mid = wn*2 + nt/4.
    float* msn = g_ms + (long)n * 3328;
    #pragma unroll
    for (int mt = 0; mt < 4; ++mt) {
        int cl0 = wm * 64 + mt * 16 + gid;   // co 0..255
        int cl1 = cl0 + 8;
        float s0 = sh3[cl0], s1 = sh3[cl1];
        float p0[4] = {0.f, 0.f, 0.f, 0.f};
        float p1[4] = {0.f, 0.f, 0.f, 0.f};
        #pragma unroll
        for (int nt = 0; nt < 8; ++nt) {
            int u = nt >> 1;
            p0[u] += lrelu(d3[mt][nt][0] + s0) + lrelu(d3[mt][nt][1] + s0);
            p1[u] += lrelu(d3[mt][nt][2] + s1) + lrelu(d3[mt][nt][3] + s1);
        }
        #pragma unroll
        for (int u = 0; u < 4; ++u) {
            p0[u] += __shfl_xor_sync(0xffffffffu, p0[u], 1);
            p0[u] += __shfl_xor_sync(0xffffffffu, p0[u], 2);
            p1[u] += __shfl_xor_sync(0xffffffffu, p1[u], 1);
            p1[u] += __shfl_xor_sync(0xffffffffu, p1[u], 2);
        }
        if (tig == 0) {
            #pragma unroll
            for (int u = 0; u < 4; ++u) {
                msn[cl0 * 8 + wn * 4 + u] = p0[u] * (1.f / 16.f);
                msn[cl1 * 8 + wn * 4 + u] = p1[u] * (1.f / 16.f);
            }
            msn[2048 + cl0 * 4 + wn * 2 + 0] = (p0[0] + p0[1]) * (1.f / 32.f);
            msn[2048 + cl0 * 4 + wn * 2 + 1] = (p0[2] + p0[3]) * (1.f / 32.f);
            msn[2048 + cl1 * 4 + wn * 2 + 0] = (p1[0] + p1[1]) * (1.f / 32.f);
            msn[2048 + cl1 * 4 + wn * 2 + 1] = (p1[2] + p1[3]) * (1.f / 32.f);
            tot[wn * 256 + cl0] = p0[0] + p0[1] + p0[2] + p0[3];
            tot[wn * 256 + cl1] = p1[0] + p1[1] + p1[2] + p1[3];
        }
    }
    __syncthreads();
    msn[3072 + tid] = (tot[tid] + tot[256 + tid]) * (1.f / 128.f);
}

// ============================================================================
// FC kernel (tf32 mma, double-buffered smem, register prefetch).
// C[M][Nc] = act(A[M][K] * B[Nc][K]^T + bias), 64x64 tile, 256 threads.
// ============================================================================
template <int K, int Nc, bool RELU>
__global__ __launch_bounds__(256) void fc_mma_kernel(
    const float* __restrict__ A, const float* __restrict__ B,
    const float* __restrict__ bias, float* __restrict__ C)
{
    __shared__ float As[2][16 * 72];   // [k][m], stride 72
    __shared__ float Bs[2][16 * 72];

    const int tid = threadIdx.x;
    const int m0 = blockIdx.y * 64, n0 = blockIdx.x * 64;
    const int lane = tid & 31, warp = tid >> 5;
    const int wm = warp >> 2, wn = warp & 3;
    const int gid = lane >> 2, tig = lane & 3;
    const int row = tid >> 2, q = tid & 3;   // staging: 64 rows x 4 k-quads

    const float* Ap = &A[(long)(m0 + row) * K + q * 4];
    const float* Bp = &B[(long)(n0 + row) * K + q * 4];

    float d[2][2][4];
    #pragma unroll
    for (int mt = 0; mt < 2; ++mt)
        #pragma unroll
        for (int nt = 0; nt < 2; ++nt)
            #pragma unroll
            for (int qq = 0; qq < 4; ++qq) d[mt][nt][qq] = 0.f;

    float4 av = *(const float4*)Ap;
    float4 bv = *(const float4*)Bp;
    {
        As[0][(q * 4 + 0) * 72 + row] = tf32r(av.x);
        As[0][(q * 4 + 1) * 72 + row] = tf32r(av.y);
        As[0][(q * 4 + 2) * 72 + row] = tf32r(av.z);
        As[0][(q * 4 + 3) * 72 + row] = tf32r(av.w);
        Bs[0][(q * 4 + 0) * 72 + row] = tf32r(bv.x);
        Bs[0][(q * 4 + 1) * 72 + row] = tf32r(bv.y);
        Bs[0][(q * 4 + 2) * 72 + row] = tf32r(bv.z);
        Bs[0][(q * 4 + 3) * 72 + row] = tf32r(bv.w);
    }
    __syncthreads();

    const int NC = K / 16;
    for (int kc = 0; kc < NC; ++kc) {
        int p = kc & 1;
        if (kc + 1 < NC) {
            av = *(const float4*)(Ap + (kc + 1) * 16);
            bv = *(const float4*)(Bp + (kc + 1) * 16);
        }
        #pragma unroll
        for (int ks = 0; ks < 2; ++ks) {
            const float* ar0 = &As[p][(ks * 8 + tig) * 72];
            const float* ar4 = &As[p][(ks * 8 + tig + 4) * 72];
            const float* br0 = &Bs[p][(ks * 8 + tig) * 72];
            const float* br4 = &Bs[p][(ks * 8 + tig + 4) * 72];
            uint32_t a[2][4];
            #pragma unroll
            for (int mt = 0; mt < 2; ++mt) {
                int m = wm * 32 + mt * 16 + gid;
                a[mt][0] = fbits(ar0[m]);  a[mt][1] = fbits(ar0[m + 8]);
                a[mt][2] = fbits(ar4[m]);  a[mt][3] = fbits(ar4[m + 8]);
            }
            #pragma unroll
            for (int nt = 0; nt < 2; ++nt) {
                int nn = wn * 16 + nt * 8 + gid;
                uint32_t b0 = fbits(br0[nn]);
                uint32_t b1 = fbits(br4[nn]);
                mma8(d[0][nt], a[0], b0, b1);
                mma8(d[1][nt], a[1], b0, b1);
            }
        }
        if (kc + 1 < NC) {
            int pn = p ^ 1;
            As[pn][(q * 4 + 0) * 72 + row] = tf32r(av.x);
            As[pn][(q * 4 + 1) * 72 + row] = tf32r(av.y);
            As[pn][(q * 4 + 2) * 72 + row] = tf32r(av.z);
            As[pn][(q * 4 + 3) * 72 + row] = tf32r(av.w);
            Bs[pn][(q * 4 + 0) * 72 + row] = tf32r(bv.x);
            Bs[pn][(q * 4 + 1) * 72 + row] = tf32r(bv.y);
            Bs[pn][(q * 4 + 2) * 72 + row] = tf32r(bv.z);
            Bs[pn][(q * 4 + 3) * 72 + row] = tf32r(bv.w);
        }
        __syncthreads();
    }

    // epilogue
    #pragma unroll
    for (int mt = 0; mt < 2; ++mt) {
        int r0 = m0 + wm * 32 + mt * 16 + gid;
        int r1 = r0 + 8;
        #pragma unroll
        for (int nt = 0; nt < 2; ++nt) {
            int nn = n0 + wn * 16 + nt * 8 + tig * 2;
            float bb0 = bias[nn], bb1 = bias[nn + 1];
            float o0 = d[mt][nt][0] + bb0, o1 = d[mt][nt][1] + bb1;
            float o2 = d[mt][nt][2] + bb0, o3 = d[mt][nt][3] + bb1;
            if (RELU) {
                o0 = fmaxf(o0, 0.f); o1 = fmaxf(o1, 0.f);
                o2 = fmaxf(o2, 0.f); o3 = fmaxf(o3, 0.f);
            }
            float2 v0 = { o0, o1 }, v1 = { o2, o3 };
            *(float2*)&C[(long)r0 * Nc + nn] = v0;
            *(float2*)&C[(long)r1 * Nc + nn] = v1;
        }
    }
}

// ============================================================================
// metadata.txt / setup_inputs() dict order:
//   0:x 1:w1 2:b1 3:w2 4:b2 5:w3 6:b3
//   7:g1 8:be1 9:m1 10:v1  11:g2 12:be2 13:m2 14:v2  15:g3 16:be3 17:m3 18:v3
//   19:lw1 20:lb1 21:lw2 22:lb2
// ============================================================================
extern "C" void kernel_launch(void* const* d_in, const int* in_sizes, int n_in,
                              void* d_out, int out_size)
{
    const float* x   = (const float*)d_in[0];
    const float* w1  = (const float*)d_in[1];
    const float* b1  = (const float*)d_in[2];
    const float* w2  = (const float*)d_in[3];
    const float* b2  = (const float*)d_in[4];
    const float* w3  = (const float*)d_in[5];
    const float* b3  = (const float*)d_in[6];
    const float* g1  = (const float*)d_in[7];
    const float* be1 = (const float*)d_in[8];
    const float* m1  = (const float*)d_in[9];
    const float* v1  = (const float*)d_in[10];
    const float* g2  = (const float*)d_in[11];
    const float* be2 = (const float*)d_in[12];
    const float* m2  = (const float*)d_in[13];
    const float* v2  = (const float*)d_in[14];
    const float* g3  = (const float*)d_in[15];
    const float* be3 = (const float*)d_in[16];
    const float* m3  = (const float*)d_in[17];
    const float* v3  = (const float*)d_in[18];
    const float* lw1 = (const float*)d_in[19];
    const float* lb1 = (const float*)d_in[20];
    const float* lw2 = (const float*)d_in[21];
    const float* lb2 = (const float*)d_in[22];
    float* out = (float*)d_out;

    const int fused_dyn = (64 * 136 + 128 * 136) * sizeof(float);  // 104448
    cudaFuncSetAttribute(fused_conv_kernel,
                         cudaFuncAttributeMaxDynamicSharedMemorySize, fused_dyn);

    prep_weights_kernel<<<384, 256>>>(w2, g2, v2, w3, g3, v3);

    fused_conv_kernel<<<1024, 256, fused_dyn>>>(
        x, w1, b1, g1, be1, m1, v1,
        b2, g2, be2, m2, v2,
        b3, g3, be3, m3, v3);

    float* fc1o;
    float* msp;
    cudaGetSymbolAddress((void**)&msp,  g_ms);
    cudaGetSymbolAddress((void**)&fc1o, g_fc1);

    fc_mma_kernel<3328, 512, true><<<dim3(8, 16), 256>>>(msp, lw1, lb1, fc1o);
    fc_mma_kernel<512, 256, false><<<dim3(4, 16), 256>>>(fc1o, lw2, lb2, out);
}

// round 12
// speedup vs baseline: 4.6307x; 1.3031x over previous
#include <cuda_runtime.h>
#include <cuda_bf16.h>
#include <cuda_fp16.h>
#include <math.h>
#include <stdint.h>

#define BN_EPS 1e-5f
#define SLOPE 0.1f

// -------- scratch (device globals; no allocation allowed) --------
__device__ float g_ms[1024 * 3328];        // pooled features
__device__ float g_fc1[1024 * 512];        // fc1 output
// fp16 fragment-major weights: [kg16][cog16][lane][8 halves]
__device__ __half g_w2h[12 * 8 * 32 * 8];   // conv2: K=192 -> 12 kg, 128 co -> 8 cog
__device__ __half g_w3h[24 * 16 * 32 * 8];  // conv3: K=384 -> 24 kg, 256 co -> 16 cog

// ---- helpers ----
__device__ __forceinline__ float tf32r(float x) {
    uint32_t u;
    asm("cvt.rna.tf32.f32 %0, %1;" : "=r"(u) : "f"(x));
    return __uint_as_float(u);
}
__device__ __forceinline__ uint32_t fbits(float x) { return __float_as_uint(x); }

// tf32 m16n8k8 (used by FC kernels)
__device__ __forceinline__ void mma8(float* d, const uint32_t* a, uint32_t b0, uint32_t b1) {
    asm volatile(
        "mma.sync.aligned.m16n8k8.row.col.f32.tf32.tf32.f32 "
        "{%0,%1,%2,%3}, {%4,%5,%6,%7}, {%8,%9}, {%0,%1,%2,%3};"
        : "+f"(d[0]), "+f"(d[1]), "+f"(d[2]), "+f"(d[3])
        : "r"(a[0]), "r"(a[1]), "r"(a[2]), "r"(a[3]), "r"(b0), "r"(b1));
}
// fp16 m16n8k16, fp32 accumulate (conv GEMMs)
__device__ __forceinline__ void mma16(float* d, const uint32_t* a, uint32_t b0, uint32_t b1) {
    asm volatile(
        "mma.sync.aligned.m16n8k16.row.col.f32.f16.f16.f32 "
        "{%0,%1,%2,%3}, {%4,%5,%6,%7}, {%8,%9}, {%0,%1,%2,%3};"
        : "+f"(d[0]), "+f"(d[1]), "+f"(d[2]), "+f"(d[3])
        : "r"(a[0]), "r"(a[1]), "r"(a[2]), "r"(a[3]), "r"(b0), "r"(b1));
}
__device__ __forceinline__ float lrelu(float v) { return v > 0.f ? v : SLOPE * v; }

// ============================================================================
// Prep: fold BN scale into w2/w3, fp16-round, pack per-lane m16n8k16 A
// fragments: halves f=0..7 -> (a0.lo,a0.hi,a1.lo,a1.hi,a2.lo,a2.hi,a3.lo,a3.hi)
//   a0={A[gid][2tig],A[gid][2tig+1]}  a1={A[gid+8][...]}
//   a2={A[gid][2tig+8],+1}            a3={A[gid+8][2tig+8],+1}
// K is tap-major: k = tap*C + ci  (k16 groups never straddle a tap).
// ============================================================================
__global__ __launch_bounds__(256) void prep_weights_kernel(
    const float* __restrict__ w2, const float* __restrict__ g2, const float* __restrict__ v2,
    const float* __restrict__ w3, const float* __restrict__ g3, const float* __restrict__ v3)
{
    int i = blockIdx.x * 256 + threadIdx.x;   // up to 98304
    if (i < 24576) {      // conv2: 12 kg x 8 cog x 32 lane x 8
        int f = i & 7, lane = (i >> 3) & 31, cog = (i >> 8) & 7, kg = i >> 11;
        int gid = lane >> 2, tig = lane & 3;
        int p = f >> 1, lo = f & 1;
        int k  = kg * 16 + 2 * tig + lo + ((p & 2) ? 8 : 0);
        int co = cog * 16 + gid + ((p & 1) ? 8 : 0);
        int tap = k >> 6, ci = k & 63;
        float a = g2[co] * rsqrtf(v2[co] + BN_EPS);
        g_w2h[i] = __float2half(a * w2[co * 192 + ci * 3 + tap]);
    }
    if (i < 98304) {      // conv3: 24 kg x 16 cog x 32 lane x 8
        int f = i & 7, lane = (i >> 3) & 31, cog = (i >> 8) & 15, kg = i >> 12;
        int gid = lane >> 2, tig = lane & 3;
        int p = f >> 1, lo = f & 1;
        int k  = kg * 16 + 2 * tig + lo + ((p & 2) ? 8 : 0);
        int co = cog * 16 + gid + ((p & 1) ? 8 : 0);
        int tap = k >> 7, ci = k & 127;
        float a = g3[co] * rsqrtf(v3[co] + BN_EPS);
        g_w3h[i] = __float2half(a * w3[co * 384 + ci * 3 + tap]);
    }
}

// ============================================================================
// FUSED kernel: conv1 (fp32) -> conv2 (fp16 mma) -> conv3 (fp16 mma) -> pools.
// grid = 1024 (one block per n), 256 threads = 8 warps as 4(M) x 2(N).
//   conv2: warp tile 32co x 64t, K=192 -> 12 k16 steps.  d2[2][8][4].
//   conv3: warp tile 64co x 64t, K=384 -> 24 k16 steps.  d3[4][8][4].
// Activations stored TRANSPOSED fp16: h1T[130][72] (t-row, ci-col, halo rows
// 0 & 129), h2T[130][136].  Strides 72/136 halves -> lane banks (4*gid+tig)
// all distinct for the half2 B loads.  A fragment = one LDS.128.
// ============================================================================
extern __shared__ float dsm[];

__global__ __launch_bounds__(256) void fused_conv_kernel(
    const float* __restrict__ x,
    const float* __restrict__ w1, const float* __restrict__ b1,
    const float* __restrict__ g1, const float* __restrict__ be1,
    const float* __restrict__ m1, const float* __restrict__ v1,
    const float* __restrict__ b2,
    const float* __restrict__ g2, const float* __restrict__ be2,
    const float* __restrict__ m2, const float* __restrict__ v2,
    const float* __restrict__ b3,
    const float* __restrict__ g3, const float* __restrict__ be3,
    const float* __restrict__ m3, const float* __restrict__ v3)
{
    __half* h1T = (__half*)dsm;             // [130][72]
    __half* h2T = h1T + 130 * 72;           // [130][136]
    __shared__ float  xs[6 * 130];
    __shared__ float  w1f[64 * 18];
    __shared__ float  sh1[64];
    __shared__ __half wsh[2][4096];         // double-buffered fragment-major chunks
    __shared__ float  sh2[128];
    __shared__ float  sh3[256];
    __shared__ float  tot[2 * 256];

    const int n   = blockIdx.x;
    const int tid = threadIdx.x;

    // ---- scales / weight folds / input tile ----
    if (tid < 64) {
        float a1 = g1[tid] * rsqrtf(v1[tid] + BN_EPS);
        sh1[tid] = a1 * (b1[tid] - m1[tid]) + be1[tid];
    }
    if (tid < 128) {
        float a2 = g2[tid] * rsqrtf(v2[tid] + BN_EPS);
        sh2[tid] = a2 * (b2[tid] - m2[tid]) + be2[tid];
    }
    {
        float a3 = g3[tid] * rsqrtf(v3[tid] + BN_EPS);
        sh3[tid] = a3 * (b3[tid] - m3[tid]) + be3[tid];
    }
    for (int i = tid; i < 64 * 18; i += 256) {
        int co = i / 18;
        float a = g1[co] * rsqrtf(v1[co] + BN_EPS);
        w1f[i] = a * w1[i];
    }
    for (int i = tid; i < 768; i += 256) {
        int t = i / 6, c = i - t * 6;
        xs[c * 130 + 1 + t] = x[n * 768 + i];
    }
    if (tid < 6)   { xs[tid * 130] = 0.f; xs[tid * 130 + 129] = 0.f; }
    if (tid < 72)  { h1T[tid] = __float2half(0.f); h1T[129 * 72 + tid] = __float2half(0.f); }
    if (tid < 136) { h2T[tid] = __float2half(0.f); h2T[129 * 136 + tid] = __float2half(0.f); }
    __syncthreads();

    // ---- conv1 + BN + lrelu -> h1T (fp16, transposed) ----
    #pragma unroll 4
    for (int r = 0; r < 32; ++r) {
        int idx = tid + 256 * r;          // 8192 = 64co x 128t
        int co = idx & 63, t = idx >> 6;
        float v = sh1[co];
        #pragma unroll
        for (int ci = 0; ci < 6; ++ci)
            #pragma unroll
            for (int k = 0; k < 3; ++k)
                v += w1f[co * 18 + ci * 3 + k] * xs[ci * 130 + t + k];
        h1T[(t + 1) * 72 + co] = __float2half(lrelu(v));
    }

    const int lane = tid & 31, warp = tid >> 5;
    const int wm = warp >> 1;            // 0..3
    const int wn = warp & 1;             // 0..1
    const int gid = lane >> 2, tig = lane & 3;

    // ================== conv2: warp tile 32co x 64t, 12 k16 steps ==========
    {
        float d2[2][8][4];
        #pragma unroll
        for (int mt = 0; mt < 2; ++mt)
            #pragma unroll
            for (int nt = 0; nt < 8; ++nt)
                #pragma unroll
                for (int q = 0; q < 4; ++q) d2[mt][nt][q] = 0.f;

        // chunk = 1 kg = 2048 halves; one uint4 (8 halves) per thread
        uint4 pv = *(const uint4*)&g_w2h[tid * 8];
        *(uint4*)&wsh[0][tid * 8] = pv;
        __syncthreads();

        for (int kg = 0; kg < 12; ++kg) {
            int p = kg & 1;
            if (kg < 11)
                pv = *(const uint4*)&g_w2h[(kg + 1) * 2048 + tid * 8];
            int tap = (kg * 16) >> 6, cib = (kg * 16) & 63;
            uint32_t a[2][4];
            #pragma unroll
            for (int mt = 0; mt < 2; ++mt) {
                uint4 av = *(const uint4*)&wsh[p][(2 * wm + mt) * 256 + lane * 8];
                a[mt][0] = av.x; a[mt][1] = av.y; a[mt][2] = av.z; a[mt][3] = av.w;
            }
            const __half* hb = h1T + (wn * 64 + gid + tap) * 72 + cib + 2 * tig;
            #pragma unroll
            for (int nt = 0; nt < 8; ++nt) {
                uint32_t b0 = *(const uint32_t*)(hb + nt * 576);       // 8*72
                uint32_t b1 = *(const uint32_t*)(hb + nt * 576 + 8);
                mma16(d2[0][nt], a[0], b0, b1);
                mma16(d2[1][nt], a[1], b0, b1);
            }
            if (kg < 11)
                *(uint4*)&wsh[p ^ 1][tid * 8] = pv;
            __syncthreads();
        }

        // epilogue: shift + lrelu -> h2T (fp16, transposed)
        #pragma unroll
        for (int mt = 0; mt < 2; ++mt) {
            int r0 = wm * 32 + mt * 16 + gid;
            int r1 = r0 + 8;
            float s0 = sh2[r0], s1 = sh2[r1];
            #pragma unroll
            for (int nt = 0; nt < 8; ++nt) {
                int t = wn * 64 + nt * 8 + tig * 2;
                h2T[(t + 1) * 136 + r0] = __float2half(lrelu(d2[mt][nt][0] + s0));
                h2T[(t + 2) * 136 + r0] = __float2half(lrelu(d2[mt][nt][1] + s0));
                h2T[(t + 1) * 136 + r1] = __float2half(lrelu(d2[mt][nt][2] + s1));
                h2T[(t + 2) * 136 + r1] = __float2half(lrelu(d2[mt][nt][3] + s1));
            }
        }
    }

    // ================== conv3: warp tile 64co x 64t, 24 k16 steps ==========
    float d3[4][8][4];
    #pragma unroll
    for (int mt = 0; mt < 4; ++mt)
        #pragma unroll
        for (int nt = 0; nt < 8; ++nt)
            #pragma unroll
            for (int q = 0; q < 4; ++q) d3[mt][nt][q] = 0.f;

    {
        // chunk = 1 kg = 4096 halves; two uint4 per thread
        uint4 pv0 = *(const uint4*)&g_w3h[tid * 8];
        uint4 pv1 = *(const uint4*)&g_w3h[2048 + tid * 8];
        *(uint4*)&wsh[0][tid * 8]        = pv0;
        *(uint4*)&wsh[0][2048 + tid * 8] = pv1;
        __syncthreads();   // covers h2T epilogue writes + wsh[0] staging

        for (int kg = 0; kg < 24; ++kg) {
            int p = kg & 1;
            if (kg < 23) {
                pv0 = *(const uint4*)&g_w3h[(kg + 1) * 4096 + tid * 8];
                pv1 = *(const uint4*)&g_w3h[(kg + 1) * 4096 + 2048 + tid * 8];
            }
            int tap = (kg * 16) >> 7, cib = (kg * 16) & 127;
            uint32_t a[4][4];
            #pragma unroll
            for (int mt = 0; mt < 4; ++mt) {
                uint4 av = *(const uint4*)&wsh[p][(4 * wm + mt) * 256 + lane * 8];
                a[mt][0] = av.x; a[mt][1] = av.y; a[mt][2] = av.z; a[mt][3] = av.w;
            }
            const __half* hb = h2T + (wn * 64 + gid + tap) * 136 + cib + 2 * tig;
            #pragma unroll
            for (int nt = 0; nt < 8; ++nt) {
                uint32_t b0 = *(const uint32_t*)(hb + nt * 1088);      // 8*136
                uint32_t b1 = *(const uint32_t*)(hb + nt * 1088 + 8);
                #pragma unroll
                for (int mt = 0; mt < 4; ++mt)
                    mma16(d3[mt][nt], a[mt], b0, b1);
            }
            if (kg < 23) {
                *(uint4*)&wsh[p ^ 1][tid * 8]        = pv0;
                *(uint4*)&wsh[p ^ 1][2048 + tid * 8] = pv1;
            }
            __syncthreads();
        }
    }

    // ---- epilogue: shift + lrelu + pools ----
    // t = wn*64 + nt*8 + tig*2 + {0,1}.  local bin = wn*4 + nt/2; mid = wn*2 + nt/4.
    float* msn = g_ms + (long)n * 3328;
    #pragma unroll
    for (int mt = 0; mt < 4; ++mt) {
        int cl0 = wm * 64 + mt * 16 + gid;   // co 0..255
        int cl1 = cl0 + 8;
        float s0 = sh3[cl0], s1 = sh3[cl1];
        float p0[4] = {0.f, 0.f, 0.f, 0.f};
        float p1[4] = {0.f, 0.f, 0.f, 0.f};
        #pragma unroll
        for (int nt = 0; nt < 8; ++nt) {
            int u = nt >> 1;
            p0[u] += lrelu(d3[mt][nt][0] + s0) + lrelu(d3[mt][nt][1] + s0);
            p1[u] += lrelu(d3[mt][nt][2] + s1) + lrelu(d3[mt][nt][3] + s1);
        }
        #pragma unroll
        for (int u = 0; u < 4; ++u) {
            p0[u] += __shfl_xor_sync(0xffffffffu, p0[u], 1);
            p0[u] += __shfl_xor_sync(0xffffffffu, p0[u], 2);
            p1[u] += __shfl_xor_sync(0xffffffffu, p1[u], 1);
            p1[u] += __shfl_xor_sync(0xffffffffu, p1[u], 2);
        }
        if (tig == 0) {
            #pragma unroll
            for (int u = 0; u < 4; ++u) {
                msn[cl0 * 8 + wn * 4 + u] = p0[u] * (1.f / 16.f);
                msn[cl1 * 8 + wn * 4 + u] = p1[u] * (1.f / 16.f);
            }
            msn[2048 + cl0 * 4 + wn * 2 + 0] = (p0[0] + p0[1]) * (1.f / 32.f);
            msn[2048 + cl0 * 4 + wn * 2 + 1] = (p0[2] + p0[3]) * (1.f / 32.f);
            msn[2048 + cl1 * 4 + wn * 2 + 0] = (p1[0] + p1[1]) * (1.f / 32.f);
            msn[2048 + cl1 * 4 + wn * 2 + 1] = (p1[2] + p1[3]) * (1.f / 32.f);
            tot[wn * 256 + cl0] = p0[0] + p0[1] + p0[2] + p0[3];
            tot[wn * 256 + cl1] = p1[0] + p1[1] + p1[2] + p1[3];
        }
    }
    __syncthreads();
    msn[3072 + tid] = (tot[tid] + tot[256 + tid]) * (1.f / 128.f);
}

// ============================================================================
// FC kernel (tf32 mma, double-buffered smem, register prefetch).
// C[M][Nc] = act(A[M][K] * B[Nc][K]^T + bias), 64x64 tile, 256 threads.
// ============================================================================
template <int K, int Nc, bool RELU>
__global__ __launch_bounds__(256) void fc_mma_kernel(
    const float* __restrict__ A, const float* __restrict__ B,
    const float* __restrict__ bias, float* __restrict__ C)
{
    __shared__ float As[2][16 * 72];   // [k][m], stride 72
    __shared__ float Bs[2][16 * 72];

    const int tid = threadIdx.x;
    const int m0 = blockIdx.y * 64, n0 = blockIdx.x * 64;
    const int lane = tid & 31, warp = tid >> 5;
    const int wm = warp >> 2, wn = warp & 3;
    const int gid = lane >> 2, tig = lane & 3;
    const int row = tid >> 2, q = tid & 3;   // staging: 64 rows x 4 k-quads

    const float* Ap = &A[(long)(m0 + row) * K + q * 4];
    const float* Bp = &B[(long)(n0 + row) * K + q * 4];

    float d[2][2][4];
    #pragma unroll
    for (int mt = 0; mt < 2; ++mt)
        #pragma unroll
        for (int nt = 0; nt < 2; ++nt)
            #pragma unroll
            for (int qq = 0; qq < 4; ++qq) d[mt][nt][qq] = 0.f;

    float4 av = *(const float4*)Ap;
    float4 bv = *(const float4*)Bp;
    {
        As[0][(q * 4 + 0) * 72 + row] = tf32r(av.x);
        As[0][(q * 4 + 1) * 72 + row] = tf32r(av.y);
        As[0][(q * 4 + 2) * 72 + row] = tf32r(av.z);
        As[0][(q * 4 + 3) * 72 + row] = tf32r(av.w);
        Bs[0][(q * 4 + 0) * 72 + row] = tf32r(bv.x);
        Bs[0][(q * 4 + 1) * 72 + row] = tf32r(bv.y);
        Bs[0][(q * 4 + 2) * 72 + row] = tf32r(bv.z);
        Bs[0][(q * 4 + 3) * 72 + row] = tf32r(bv.w);
    }
    __syncthreads();

    const int NC = K / 16;
    for (int kc = 0; kc < NC; ++kc) {
        int p = kc & 1;
        if (kc + 1 < NC) {
            av = *(const float4*)(Ap + (kc + 1) * 16);
            bv = *(const float4*)(Bp + (kc + 1) * 16);
        }
        #pragma unroll
        for (int ks = 0; ks < 2; ++ks) {
            const float* ar0 = &As[p][(ks * 8 + tig) * 72];
            const float* ar4 = &As[p][(ks * 8 + tig + 4) * 72];
            const float* br0 = &Bs[p][(ks * 8 + tig) * 72];
            const float* br4 = &Bs[p][(ks * 8 + tig + 4) * 72];
            uint32_t a[2][4];
            #pragma unroll
            for (int mt = 0; mt < 2; ++mt) {
                int m = wm * 32 + mt * 16 + gid;
                a[mt][0] = fbits(ar0[m]);  a[mt][1] = fbits(ar0[m + 8]);
                a[mt][2] = fbits(ar4[m]);  a[mt][3] = fbits(ar4[m + 8]);
            }
            #pragma unroll
            for (int nt = 0; nt < 2; ++nt) {
                int nn = wn * 16 + nt * 8 + gid;
                uint32_t b0 = fbits(br0[nn]);
                uint32_t b1 = fbits(br4[nn]);
                mma8(d[0][nt], a[0], b0, b1);
                mma8(d[1][nt], a[1], b0, b1);
            }
        }
        if (kc + 1 < NC) {
            int pn = p ^ 1;
            As[pn][(q * 4 + 0) * 72 + row] = tf32r(av.x);
            As[pn][(q * 4 + 1) * 72 + row] = tf32r(av.y);
            As[pn][(q * 4 + 2) * 72 + row] = tf32r(av.z);
            As[pn][(q * 4 + 3) * 72 + row] = tf32r(av.w);
            Bs[pn][(q * 4 + 0) * 72 + row] = tf32r(bv.x);
            Bs[pn][(q * 4 + 1) * 72 + row] = tf32r(bv.y);
            Bs[pn][(q * 4 + 2) * 72 + row] = tf32r(bv.z);
            Bs[pn][(q * 4 + 3) * 72 + row] = tf32r(bv.w);
        }
        __syncthreads();
    }

    // epilogue
    #pragma unroll
    for (int mt = 0; mt < 2; ++mt) {
        int r0 = m0 + wm * 32 + mt * 16 + gid;
        int r1 = r0 + 8;
        #pragma unroll
        for (int nt = 0; nt < 2; ++nt) {
            int nn = n0 + wn * 16 + nt * 8 + tig * 2;
            float bb0 = bias[nn], bb1 = bias[nn + 1];
            float o0 = d[mt][nt][0] + bb0, o1 = d[mt][nt][1] + bb1;
            float o2 = d[mt][nt][2] + bb0, o3 = d[mt][nt][3] + bb1;
            if (RELU) {
                o0 = fmaxf(o0, 0.f); o1 = fmaxf(o1, 0.f);
                o2 = fmaxf(o2, 0.f); o3 = fmaxf(o3, 0.f);
            }
            float2 v0 = { o0, o1 }, v1 = { o2, o3 };
            *(float2*)&C[(long)r0 * Nc + nn] = v0;
            *(float2*)&C[(long)r1 * Nc + nn] = v1;
        }
    }
}

// ============================================================================
// metadata.txt / setup_inputs() dict order:
//   0:x 1:w1 2:b1 3:w2 4:b2 5:w3 6:b3
//   7:g1 8:be1 9:m1 10:v1  11:g2 12:be2 13:m2 14:v2  15:g3 16:be3 17:m3 18:v3
//   19:lw1 20:lb1 21:lw2 22:lb2
// ============================================================================
extern "C" void kernel_launch(void* const* d_in, const int* in_sizes, int n_in,
                              void* d_out, int out_size)
{
    const float* x   = (const float*)d_in[0];
    const float* w1  = (const float*)d_in[1];
    const float* b1  = (const float*)d_in[2];
    const float* w2  = (const float*)d_in[3];
    const float* b2  = (const float*)d_in[4];
    const float* w3  = (const float*)d_in[5];
    const float* b3  = (const float*)d_in[6];
    const float* g1  = (const float*)d_in[7];
    const float* be1 = (const float*)d_in[8];
    const float* m1  = (const float*)d_in[9];
    const float* v1  = (const float*)d_in[10];
    const float* g2  = (const float*)d_in[11];
    const float* be2 = (const float*)d_in[12];
    const float* m2  = (const float*)d_in[13];
    const float* v2  = (const float*)d_in[14];
    const float* g3  = (const float*)d_in[15];
    const float* be3 = (const float*)d_in[16];
    const float* m3  = (const float*)d_in[17];
    const float* v3  = (const float*)d_in[18];
    const float* lw1 = (const float*)d_in[19];
    const float* lb1 = (const float*)d_in[20];
    const float* lw2 = (const float*)d_in[21];
    const float* lb2 = (const float*)d_in[22];
    float* out = (float*)d_out;

    // h1T 130*72 + h2T 130*136 halves = 54080 bytes dynamic
    const int fused_dyn = (130 * 72 + 130 * 136) * sizeof(__half);
    cudaFuncSetAttribute(fused_conv_kernel,
                         cudaFuncAttributeMaxDynamicSharedMemorySize, fused_dyn);

    prep_weights_kernel<<<384, 256>>>(w2, g2, v2, w3, g3, v3);

    fused_conv_kernel<<<1024, 256, fused_dyn>>>(
        x, w1, b1, g1, be1, m1, v1,
        b2, g2, be2, m2, v2,
        b3, g3, be3, m3, v3);

    float* fc1o;
    float* msp;
    cudaGetSymbolAddress((void**)&msp,  g_ms);
    cudaGetSymbolAddress((void**)&fc1o, g_fc1);

    fc_mma_kernel<3328, 512, true><<<dim3(8, 16), 256>>>(msp, lw1, lb1, fc1o);
    fc_mma_kernel<512, 256, false><<<dim3(4, 16), 256>>>(fc1o, lw2, lb2, out);
}